// round 11
// baseline (speedup 1.0000x reference)
#include <cuda_runtime.h>
#include <cuda_bf16.h>
#include <cuda_fp16.h>
#include <math.h>
#include <stdint.h>

// Problem constants
#define BB 2
#define TT 4096
#define DD 2048
#define NHEAD 8
#define HD 256
#define TOK (BB*TT)           // 8192
#define NQKV 2560             // 8*256 Q + 256 K + 256 V

// ---------------- scratch (device globals; no allocation allowed) ----------
__device__ __nv_bfloat16 g_Qsp[(size_t)2 * TOK * DD];   // 64 MiB (hi | lo)
__device__ __nv_bfloat16 g_Ahi[(size_t)TOK * DD];       // 32 MiB
__device__ __nv_bfloat16 g_Alo[(size_t)TOK * DD];       // 32 MiB
__device__ __nv_bfloat16 g_Bhi[(size_t)NQKV * DD];      // 10 MiB
__device__ __nv_bfloat16 g_Blo[(size_t)NQKV * DD];      // 10 MiB
__device__ __nv_bfloat16 g_Khi[(size_t)TOK * HD];       // 4 MiB
__device__ __nv_bfloat16 g_Klo[(size_t)TOK * HD];       // 4 MiB
__device__ __half        g_Vh [(size_t)TOK * HD];       // 4 MiB
__device__ float2        g_ropetab[(size_t)TT * 128];   // 4 MiB

// =================== ptx helpers ========================
__device__ __forceinline__ uint32_t s2u(const void* p) {
    uint32_t a;
    asm("{ .reg .u64 t; cvta.to.shared.u64 t, %1; cvt.u32.u64 %0, t; }"
        : "=r"(a) : "l"(p));
    return a;
}
__device__ __forceinline__ void cpa16(uint32_t s, const void* g) {
    asm volatile("cp.async.cg.shared.global [%0], [%1], 16;" :: "r"(s), "l"(g));
}
#define CP_COMMIT()  asm volatile("cp.async.commit_group;" ::: "memory")
#define CP_WAIT(N)   asm volatile("cp.async.wait_group %0;" :: "n"(N) : "memory")

#define LDSM4(r0, r1, r2, r3, addr) \
    asm volatile("ldmatrix.sync.aligned.m8n8.x4.shared.b16 {%0,%1,%2,%3}, [%4];" \
                 : "=r"(r0), "=r"(r1), "=r"(r2), "=r"(r3) : "r"(addr))

#define LDSM4T(r0, r1, r2, r3, addr) \
    asm volatile("ldmatrix.sync.aligned.m8n8.x4.trans.shared.b16 {%0,%1,%2,%3}, [%4];" \
                 : "=r"(r0), "=r"(r1), "=r"(r2), "=r"(r3) : "r"(addr))

#define MMA16816(d, a, b0, b1) \
    asm volatile("mma.sync.aligned.m16n8k16.row.col.f32.bf16.bf16.f32 " \
                 "{%0,%1,%2,%3}, {%4,%5,%6,%7}, {%8,%9}, {%0,%1,%2,%3};" \
                 : "+f"((d)[0]), "+f"((d)[1]), "+f"((d)[2]), "+f"((d)[3]) \
                 : "r"((a)[0]), "r"((a)[1]), "r"((a)[2]), "r"((a)[3]), \
                   "r"(b0), "r"(b1))

#define MMAF16(d, a, b0, b1) \
    asm volatile("mma.sync.aligned.m16n8k16.row.col.f32.f16.f16.f32 " \
                 "{%0,%1,%2,%3}, {%4,%5,%6,%7}, {%8,%9}, {%0,%1,%2,%3};" \
                 : "+f"((d)[0]), "+f"((d)[1]), "+f"((d)[2]), "+f"((d)[3]) \
                 : "r"((a)[0]), "r"((a)[1]), "r"((a)[2]), "r"((a)[3]), \
                   "r"(b0), "r"(b1))

// ===========================================================================
// RoPE table
// ===========================================================================
__global__ void rope_table() {
    __shared__ double u1s;
    const int i = blockIdx.x;
    if (threadIdx.x == 0)
        u1s = pow(10000.0, -(double)i / 128.0) * 0.15915494309189533576;
    __syncthreads();
    const double u1 = u1s;
    for (int t = threadIdx.x; t < TT; t += blockDim.x) {
        double u = (double)t * u1;
        float x2 = (float)(2.0 * (u - trunc(u)));
        float s, c;
        sincospif(x2, &s, &c);
        g_ropetab[t * 128 + i] = make_float2(s, c);
    }
}

// ===========================================================================
// Weight prep (unchanged from R10)
// ===========================================================================
__global__ void transpose_qkvw(const float* __restrict__ qw,
                               const float* __restrict__ kvw) {
    __shared__ float t[32][33];
    const int g = blockIdx.z;
    const float* slab = (g < 8) ? qw + (size_t)g * DD * HD
                                : kvw + (size_t)(g - 8) * DD * HD;
    const int h0 = blockIdx.x * 32, k0 = blockIdx.y * 32;
    const int c = threadIdx.x, r0 = threadIdx.y;
#pragma unroll
    for (int i = 0; i < 32; i += 8)
        t[r0 + i][c] = slab[(size_t)(k0 + r0 + i) * HD + h0 + c];
    __syncthreads();
#pragma unroll
    for (int i = 0; i < 32; i += 8) {
        float v = t[c][r0 + i];
        int h = h0 + r0 + i;
        int hp = (g == 9) ? h : ((h < 128) ? 2 * h : 2 * (h - 128) + 1);
        size_t o = (size_t)(g * 256 + hp) * DD + k0 + c;
        __nv_bfloat16 hi = __float2bfloat16(v);
        g_Bhi[o] = hi;
        g_Blo[o] = __float2bfloat16(v - __bfloat162float(hi));
    }
}

__global__ void transpose_outw(const float* __restrict__ ow) {
    __shared__ float t[32][33];
    const int j0 = blockIdx.x * 32, k0 = blockIdx.y * 32;
    const int c = threadIdx.x, r0 = threadIdx.y;
#pragma unroll
    for (int i = 0; i < 32; i += 8)
        t[r0 + i][c] = ow[(size_t)(k0 + r0 + i) * DD + j0 + c];
    __syncthreads();
#pragma unroll
    for (int i = 0; i < 32; i += 8) {
        float v = t[c][r0 + i];
        size_t o = (size_t)(j0 + r0 + i) * DD + k0 + c;
        __nv_bfloat16 hi = __float2bfloat16(v);
        g_Bhi[o] = hi;
        g_Blo[o] = __float2bfloat16(v - __bfloat162float(hi));
    }
}

__global__ void convert_split(const float* __restrict__ src) {
    size_t i = (size_t)blockIdx.x * blockDim.x + threadIdx.x;
    float4 v = ((const float4*)src)[i];
    __nv_bfloat16 hx = __float2bfloat16(v.x), hy = __float2bfloat16(v.y);
    __nv_bfloat16 hz = __float2bfloat16(v.z), hw = __float2bfloat16(v.w);
    __nv_bfloat162* h2 = (__nv_bfloat162*)g_Ahi;
    __nv_bfloat162* l2 = (__nv_bfloat162*)g_Alo;
    h2[2 * i]     = __halves2bfloat162(hx, hy);
    h2[2 * i + 1] = __halves2bfloat162(hz, hw);
    l2[2 * i]     = __halves2bfloat162(
        __float2bfloat16(v.x - __bfloat162float(hx)),
        __float2bfloat16(v.y - __bfloat162float(hy)));
    l2[2 * i + 1] = __halves2bfloat162(
        __float2bfloat16(v.z - __bfloat162float(hz)),
        __float2bfloat16(v.w - __bfloat162float(hw)));
}

// ===========================================================================
// HMMA 3xBF16 GEMM — 3-stage cp.async ring (prefetch distance 2), one
// barrier per iteration.
// ===========================================================================
#define KC 32
#define TROW 80
#define TILEB (128 * TROW)
#define STAGEB (4 * TILEB)          // 40960
#define GSM_TOTAL (3 * STAGEB)      // 122880

__device__ __forceinline__ void load_stage(uint32_t smb, int s, int k0, int tid,
                                           const __nv_bfloat16* const* base) {
    uint32_t sb = smb + s * STAGEB;
#pragma unroll
    for (int j = 0; j < 8; ++j) {
        int c = tid + j * 256;
        const int tile = j >> 1;
        int inner = c & 511;
        int row = inner >> 2, seg = inner & 3;
        const __nv_bfloat16* gp = base[tile] + (size_t)row * DD + k0 + seg * 8;
        cpa16(sb + tile * TILEB + row * TROW + seg * 16, gp);
    }
    CP_COMMIT();
}

__global__ __launch_bounds__(256, 1) void gemm3x_kernel(float* outp, int mode) {
    extern __shared__ __align__(128) char sm[];
    uint32_t smb = s2u(sm);
    const int tid = threadIdx.x;
    const int lane = tid & 31, wid = tid >> 5;
    const int wm = wid & 1, wn = wid >> 1;
    const int n0 = blockIdx.x * 128;
    const int m0 = blockIdx.y * 128;

    const __nv_bfloat16* base[4] = {
        g_Ahi + (size_t)m0 * DD, g_Alo + (size_t)m0 * DD,
        g_Bhi + (size_t)n0 * DD, g_Blo + (size_t)n0 * DD };

    float acc[4][4][4];
#pragma unroll
    for (int i = 0; i < 4; ++i)
#pragma unroll
        for (int j = 0; j < 4; ++j)
#pragma unroll
            for (int r = 0; r < 4; ++r) acc[i][j][r] = 0.f;

    const uint32_t a_off = (uint32_t)((wm * 64 + (lane & 15)) * TROW
                                      + (lane >> 4) * 16);
    const uint32_t b_off = (uint32_t)((wn * 32 + (lane >> 4) * 8 + (lane & 7)) * TROW
                                      + ((lane >> 3) & 1) * 16);

    load_stage(smb, 0, 0, tid, base);
    load_stage(smb, 1, KC, tid, base);

    const int NIT = DD / KC;   // 64
    int s = 0;
    for (int it = 0; it < NIT; ++it) {
        if (it == NIT - 1) { CP_WAIT(0); } else { CP_WAIT(1); }
        __syncthreads();   // stage s ready; slot (it+2)%3 fully consumed
        if (it + 2 < NIT)
            load_stage(smb, (s + 2 >= 3) ? s - 1 : s + 2, (it + 2) * KC, tid, base);

        const uint32_t st = smb + s * STAGEB;
#pragma unroll
        for (int ks = 0; ks < 2; ++ks) {
            const uint32_t ko = ks * 32;
            uint32_t ahi[4][4], alo[4][4];
#pragma unroll
            for (int mf = 0; mf < 4; ++mf) {
                uint32_t aa = st + a_off + mf * (16 * TROW) + ko;
                LDSM4(ahi[mf][0], ahi[mf][1], ahi[mf][2], ahi[mf][3], aa);
                LDSM4(alo[mf][0], alo[mf][1], alo[mf][2], alo[mf][3], aa + TILEB);
            }
            uint32_t bhi[4][2], blo[4][2];
#pragma unroll
            for (int pr = 0; pr < 2; ++pr) {
                uint32_t ba = st + 2 * TILEB + b_off + pr * (16 * TROW) + ko;
                LDSM4(bhi[2 * pr][0], bhi[2 * pr][1],
                      bhi[2 * pr + 1][0], bhi[2 * pr + 1][1], ba);
                LDSM4(blo[2 * pr][0], blo[2 * pr][1],
                      blo[2 * pr + 1][0], blo[2 * pr + 1][1], ba + TILEB);
            }
#pragma unroll
            for (int mf = 0; mf < 4; ++mf)
#pragma unroll
                for (int nf = 0; nf < 4; ++nf) {
                    MMA16816(acc[mf][nf], ahi[mf], bhi[nf][0], bhi[nf][1]);
                    MMA16816(acc[mf][nf], ahi[mf], blo[nf][0], blo[nf][1]);
                    MMA16816(acc[mf][nf], alo[mf], bhi[nf][0], bhi[nf][1]);
                }
        }
        s = (s == 2) ? 0 : s + 1;
    }
    __syncthreads();

    const int r0 = m0 + wm * 64 + (lane >> 2);
    const int lc0 = wn * 32 + 2 * (lane & 3);

    if (mode == 1) {
        const int c0 = n0 + lc0;
#pragma unroll
        for (int mf = 0; mf < 4; ++mf)
#pragma unroll
            for (int nf = 0; nf < 4; ++nf) {
                float* p0 = outp + (size_t)(r0 + mf * 16) * DD + c0 + nf * 8;
                *(float2*)p0 = make_float2(acc[mf][nf][0], acc[mf][nf][1]);
                float* p1 = p0 + 8 * DD;
                *(float2*)p1 = make_float2(acc[mf][nf][2], acc[mf][nf][3]);
            }
    } else if (n0 < 2048) {
        __nv_bfloat16* Qhi = g_Qsp;
        __nv_bfloat16* Qlo = g_Qsp + (size_t)TOK * DD;
#pragma unroll
        for (int mf = 0; mf < 4; ++mf)
#pragma unroll
            for (int nf = 0; nf < 4; ++nf) {
                int row1 = r0 + mf * 16, row2 = row1 + 8;
                int col = n0 + lc0 + nf * 8;
                int ri = (col & 255) >> 1;
                float2 sc1 = g_ropetab[(row1 & (TT - 1)) * 128 + ri];
                float2 sc2 = g_ropetab[(row2 & (TT - 1)) * 128 + ri];
                float a1 = acc[mf][nf][0], b1 = acc[mf][nf][1];
                float a2 = acc[mf][nf][2], b2 = acc[mf][nf][3];
                float x1 = (a1 * sc1.y - b1 * sc1.x) * 0.0625f;
                float y1 = (b1 * sc1.y + a1 * sc1.x) * 0.0625f;
                float x2 = (a2 * sc2.y - b2 * sc2.x) * 0.0625f;
                float y2 = (b2 * sc2.y + a2 * sc2.x) * 0.0625f;
                __nv_bfloat16 hx1 = __float2bfloat16(x1), hy1 = __float2bfloat16(y1);
                __nv_bfloat16 hx2 = __float2bfloat16(x2), hy2 = __float2bfloat16(y2);
                *(__nv_bfloat162*)&Qhi[(size_t)row1 * DD + col] = __halves2bfloat162(hx1, hy1);
                *(__nv_bfloat162*)&Qhi[(size_t)row2 * DD + col] = __halves2bfloat162(hx2, hy2);
                *(__nv_bfloat162*)&Qlo[(size_t)row1 * DD + col] = __halves2bfloat162(
                    __float2bfloat16(x1 - __bfloat162float(hx1)),
                    __float2bfloat16(y1 - __bfloat162float(hy1)));
                *(__nv_bfloat162*)&Qlo[(size_t)row2 * DD + col] = __halves2bfloat162(
                    __float2bfloat16(x2 - __bfloat162float(hx2)),
                    __float2bfloat16(y2 - __bfloat162float(hy2)));
            }
    } else if (n0 < 2304) {
#pragma unroll
        for (int mf = 0; mf < 4; ++mf)
#pragma unroll
            for (int nf = 0; nf < 4; ++nf) {
                int row1 = r0 + mf * 16, row2 = row1 + 8;
                int col = (n0 - 2048) + lc0 + nf * 8;
                int ri = col >> 1;
                float2 sc1 = g_ropetab[(row1 & (TT - 1)) * 128 + ri];
                float2 sc2 = g_ropetab[(row2 & (TT - 1)) * 128 + ri];
                float a1 = acc[mf][nf][0], b1 = acc[mf][nf][1];
                float a2 = acc[mf][nf][2], b2 = acc[mf][nf][3];
                float x1 = a1 * sc1.y - b1 * sc1.x;
                float y1 = b1 * sc1.y + a1 * sc1.x;
                float x2 = a2 * sc2.y - b2 * sc2.x;
                float y2 = b2 * sc2.y + a2 * sc2.x;
                __nv_bfloat16 hx1 = __float2bfloat16(x1), hy1 = __float2bfloat16(y1);
                __nv_bfloat16 hx2 = __float2bfloat16(x2), hy2 = __float2bfloat16(y2);
                *(__nv_bfloat162*)&g_Khi[(size_t)row1 * HD + col] = __halves2bfloat162(hx1, hy1);
                *(__nv_bfloat162*)&g_Khi[(size_t)row2 * HD + col] = __halves2bfloat162(hx2, hy2);
                *(__nv_bfloat162*)&g_Klo[(size_t)row1 * HD + col] = __halves2bfloat162(
                    __float2bfloat16(x1 - __bfloat162float(hx1)),
                    __float2bfloat16(y1 - __bfloat162float(hy1)));
                *(__nv_bfloat162*)&g_Klo[(size_t)row2 * HD + col] = __halves2bfloat162(
                    __float2bfloat16(x2 - __bfloat162float(hx2)),
                    __float2bfloat16(y2 - __bfloat162float(hy2)));
            }
    } else {
#pragma unroll
        for (int mf = 0; mf < 4; ++mf)
#pragma unroll
            for (int nf = 0; nf < 4; ++nf) {
                int row1 = r0 + mf * 16, row2 = row1 + 8;
                int col = (n0 - 2304) + lc0 + nf * 8;
                *(__half2*)&g_Vh[(size_t)row1 * HD + col] =
                    __floats2half2_rn(acc[mf][nf][0], acc[mf][nf][1]);
                *(__half2*)&g_Vh[(size_t)row2 * HD + col] =
                    __floats2half2_rn(acc[mf][nf][2], acc[mf][nf][3]);
            }
    }
}

// ===========================================================================
// HMMA causal flash attention — 3-stage K/V ring (prefetch distance 2).
// ===========================================================================
#define BN 32
#define KST 528
#define PST 80
#define FSTAGE 50688
#define ST_KHI(s) ((s)*FSTAGE)
#define ST_KLO(s) (ST_KHI(s)+16896)
#define ST_VH(s)  (ST_KHI(s)+33792)
#define SQLO   (3*FSTAGE)               // 152064
#define SPHI   (SQLO + 33792)           // 185856
#define SRED   (SPHI + 64*PST)          // 190976
#define FLASH_SMEM (SRED + 1024)        // 192000

__device__ __forceinline__ void flash_load(uint32_t smb, int s, int s0, int tid,
                                           const __nv_bfloat16* kh,
                                           const __nv_bfloat16* kl,
                                           const __half* vh) {
#pragma unroll
    for (int i2 = 0; i2 < 4; ++i2) {
        int c = tid + i2 * 256;
        int row = c >> 5, seg = c & 31;
        size_t go = (size_t)(s0 + row) * 512 + seg * 16;
        uint32_t so = row * KST + seg * 16;
        cpa16(smb + ST_KHI(s) + so, (const char*)kh + go);
        cpa16(smb + ST_KLO(s) + so, (const char*)kl + go);
        cpa16(smb + ST_VH(s)  + so, (const char*)vh + go);
    }
    CP_COMMIT();
}

__global__ __launch_bounds__(256) void flash_hmma() {
    extern __shared__ __align__(128) char sm[];
    uint32_t smb = s2u(sm);
    const int tid = threadIdx.x, lane = tid & 31, wid = tid >> 5;
    const int wm = wid >> 1, wn = wid & 1;
    const int bx = gridDim.x - 1 - blockIdx.x;
    const int n = blockIdx.y, b = blockIdx.z;
    const int q0 = bx * 64;
    const size_t tb = (size_t)b * TT;

    const char* qh_g = (const char*)(g_Qsp + (size_t)(tb + q0) * DD + n * 256);
    const char* ql_g = (const char*)(g_Qsp + (size_t)TOK * DD
                                     + (size_t)(tb + q0) * DD + n * 256);
    const __nv_bfloat16* kh_g = g_Khi + tb * 256;
    const __nv_bfloat16* kl_g = g_Klo + tb * 256;
    const __half* vh_g = g_Vh + tb * 256;

    // ---- stage Q: hi -> stage-2 K/V slot (transient), lo -> SQLO
#pragma unroll
    for (int i2 = 0; i2 < 8; ++i2) {
        int c = tid + i2 * 256;
        int row = c >> 5, seg = c & 31;
        cpa16(smb + ST_KHI(2) + row * KST + seg * 16, qh_g + (size_t)row * 4096 + seg * 16);
        cpa16(smb + SQLO + row * KST + seg * 16,      ql_g + (size_t)row * 4096 + seg * 16);
    }
    CP_COMMIT();
    CP_WAIT(0);
    __syncthreads();

    const uint32_t a_base = (uint32_t)((wm * 16 + (lane & 15)) * KST + (lane >> 4) * 16);
    uint32_t qh[16][4];
#pragma unroll
    for (int ks = 0; ks < 16; ++ks)
        LDSM4(qh[ks][0], qh[ks][1], qh[ks][2], qh[ks][3],
              smb + ST_KHI(2) + a_base + ks * 32);
    __syncthreads();   // Qhi consumed; stage 2 free

    const int ntiles = 2 * bx + 2;
    flash_load(smb, 0, 0, tid, kh_g, kl_g, vh_g);
    if (ntiles > 1) flash_load(smb, 1, BN, tid, kh_g, kl_g, vh_g);

    float o[16][4];
#pragma unroll
    for (int nf = 0; nf < 16; ++nf)
#pragma unroll
        for (int r = 0; r < 4; ++r) o[nf][r] = 0.f;
    float m1 = -1e30f, m2 = -1e30f, l1 = 0.f, l2 = 0.f;

    const int grow1 = wm * 16 + (lane >> 2);
    const int grow2 = grow1 + 8;
    const int ccol = 2 * (lane & 3);
    float* rmaxs = (float*)(sm + SRED);
    float* rsums = (float*)(sm + SRED + 512);
    const uint32_t b_base = (uint32_t)((wn * 16 + ((lane >> 4) << 3) + (lane & 7)) * KST
                                       + ((lane >> 3) & 1) * 16);
    const uint32_t p_base = (uint32_t)((wm * 16 + (lane & 15)) * PST + (lane >> 4) * 16);
    const uint32_t v_base = (uint32_t)((lane & 15) * KST + wn * 256 + (lane >> 4) * 16);

    int s = 0;
    for (int kt = 0; kt < ntiles; ++kt) {
        if (kt == ntiles - 1) { CP_WAIT(0); } else { CP_WAIT(1); }
        __syncthreads();   // stage s ready; slot (kt+2)%3 consumed (iter kt-1)
        if (kt + 2 < ntiles)
            flash_load(smb, (s + 2 >= 3) ? s - 1 : s + 2, (kt + 2) * BN,
                       tid, kh_g, kl_g, vh_g);

        // ---- S = Q K^T (3x split)
        float sa[2][4];
#pragma unroll
        for (int nf = 0; nf < 2; ++nf)
#pragma unroll
            for (int r = 0; r < 4; ++r) sa[nf][r] = 0.f;
#pragma unroll
        for (int ks = 0; ks < 16; ++ks) {
            uint32_t ql[4];
            LDSM4(ql[0], ql[1], ql[2], ql[3], smb + SQLO + a_base + ks * 32);
            uint32_t bh0, bh1, bh2, bh3, bl0, bl1, bl2, bl3;
            LDSM4(bh0, bh1, bh2, bh3, smb + ST_KHI(s) + b_base + ks * 32);
            LDSM4(bl0, bl1, bl2, bl3, smb + ST_KLO(s) + b_base + ks * 32);
            MMA16816(sa[0], qh[ks], bh0, bh1);
            MMA16816(sa[1], qh[ks], bh2, bh3);
            MMA16816(sa[0], qh[ks], bl0, bl1);
            MMA16816(sa[1], qh[ks], bl2, bl3);
            MMA16816(sa[0], ql, bh0, bh1);
            MMA16816(sa[1], ql, bh2, bh3);
        }

        // ---- causal mask (only last two tiles)
        const int s0 = kt * BN;
        if (kt >= 2 * bx) {
            const int qr1 = q0 + grow1, qr2 = q0 + grow2;
#pragma unroll
            for (int nf = 0; nf < 2; ++nf) {
                int c0 = s0 + wn * 16 + nf * 8 + ccol;
                if (c0     > qr1) sa[nf][0] = -1e30f;
                if (c0 + 1 > qr1) sa[nf][1] = -1e30f;
                if (c0     > qr2) sa[nf][2] = -1e30f;
                if (c0 + 1 > qr2) sa[nf][3] = -1e30f;
            }
        }

        // ---- online softmax
        float pm1 = fmaxf(fmaxf(sa[0][0], sa[0][1]), fmaxf(sa[1][0], sa[1][1]));
        float pm2 = fmaxf(fmaxf(sa[0][2], sa[0][3]), fmaxf(sa[1][2], sa[1][3]));
        pm1 = fmaxf(pm1, __shfl_xor_sync(0xffffffffu, pm1, 1));
        pm1 = fmaxf(pm1, __shfl_xor_sync(0xffffffffu, pm1, 2));
        pm2 = fmaxf(pm2, __shfl_xor_sync(0xffffffffu, pm2, 1));
        pm2 = fmaxf(pm2, __shfl_xor_sync(0xffffffffu, pm2, 2));
        if ((lane & 3) == 0) {
            rmaxs[wn * 64 + grow1] = pm1;
            rmaxs[wn * 64 + grow2] = pm2;
        }
        __syncthreads();
        float mn1 = fmaxf(m1, fmaxf(rmaxs[grow1], rmaxs[64 + grow1]));
        float mn2 = fmaxf(m2, fmaxf(rmaxs[grow2], rmaxs[64 + grow2]));
        float al1 = __expf(m1 - mn1), al2 = __expf(m2 - mn2);
        m1 = mn1; m2 = mn2;

        float ps1 = 0.f, ps2 = 0.f;
#pragma unroll
        for (int nf = 0; nf < 2; ++nf) {
            float e0 = __expf(sa[nf][0] - mn1), e1 = __expf(sa[nf][1] - mn1);
            float e2 = __expf(sa[nf][2] - mn2), e3 = __expf(sa[nf][3] - mn2);
            ps1 += e0 + e1; ps2 += e2 + e3;
            int colB = (wn * 16 + nf * 8 + ccol) * 2;
            *(__half2*)(sm + SPHI + grow1 * PST + colB) = __floats2half2_rn(e0, e1);
            *(__half2*)(sm + SPHI + grow2 * PST + colB) = __floats2half2_rn(e2, e3);
        }
        ps1 += __shfl_xor_sync(0xffffffffu, ps1, 1);
        ps1 += __shfl_xor_sync(0xffffffffu, ps1, 2);
        ps2 += __shfl_xor_sync(0xffffffffu, ps2, 1);
        ps2 += __shfl_xor_sync(0xffffffffu, ps2, 2);
        if ((lane & 3) == 0) {
            rsums[wn * 64 + grow1] = ps1;
            rsums[wn * 64 + grow2] = ps2;
        }
#pragma unroll
        for (int nf = 0; nf < 16; ++nf) {
            o[nf][0] *= al1; o[nf][1] *= al1;
            o[nf][2] *= al2; o[nf][3] *= al2;
        }
        __syncthreads();
        l1 = l1 * al1 + rsums[grow1] + rsums[64 + grow1];
        l2 = l2 * al2 + rsums[grow2] + rsums[64 + grow2];

        // ---- O += P V  (fp16 P)
#pragma unroll
        for (int ks = 0; ks < 2; ++ks) {
            uint32_t ph[4];
            LDSM4(ph[0], ph[1], ph[2], ph[3], smb + SPHI + p_base + ks * 32);
#pragma unroll
            for (int nb = 0; nb < 8; ++nb) {
                uint32_t v0, v1, v2, v3;
                LDSM4T(v0, v1, v2, v3,
                       smb + ST_VH(s) + v_base + ks * (16 * KST) + nb * 32);
                MMAF16(o[2 * nb],     ph, v0, v1);
                MMAF16(o[2 * nb + 1], ph, v2, v3);
            }
        }
        s = (s == 2) ? 0 : s + 1;
    }

    // ---- epilogue: normalize, bf16 split into out-GEMM A buffers
    float i1 = 1.f / l1, i2 = 1.f / l2;
#pragma unroll
    for (int nf = 0; nf < 16; ++nf) {
        int col = n * 256 + wn * 128 + nf * 8 + ccol;
        size_t o1 = (tb + q0 + grow1) * (size_t)DD + col;
        size_t o2 = (tb + q0 + grow2) * (size_t)DD + col;
        float v0 = o[nf][0] * i1, v1 = o[nf][1] * i1;
        float v2 = o[nf][2] * i2, v3 = o[nf][3] * i2;
        __nv_bfloat16 h0 = __float2bfloat16(v0), h1 = __float2bfloat16(v1);
        __nv_bfloat16 h2 = __float2bfloat16(v2), h3 = __float2bfloat16(v3);
        *(__nv_bfloat162*)&g_Ahi[o1] = __halves2bfloat162(h0, h1);
        *(__nv_bfloat162*)&g_Ahi[o2] = __halves2bfloat162(h2, h3);
        *(__nv_bfloat162*)&g_Alo[o1] = __halves2bfloat162(
            __float2bfloat16(v0 - __bfloat162float(h0)),
            __float2bfloat16(v1 - __bfloat162float(h1)));
        *(__nv_bfloat162*)&g_Alo[o2] = __halves2bfloat162(
            __float2bfloat16(v2 - __bfloat162float(h2)),
            __float2bfloat16(v3 - __bfloat162float(h3)));
    }
}

// ===========================================================================
// launch — inputs: 0=x, 1=segment_pos, 2=attn_mask, 3=q_w, 4=kv_w, 5=out_w
// ===========================================================================
extern "C" void kernel_launch(void* const* d_in, const int* in_sizes, int n_in,
                              void* d_out, int out_size) {
    (void)in_sizes; (void)n_in; (void)out_size;
    const float* x   = (const float*)d_in[0];
    const float* qw  = (const float*)d_in[3];
    const float* kvw = (const float*)d_in[4];
    const float* ow  = (const float*)d_in[5];
    float* out = (float*)d_out;

    cudaFuncSetAttribute(gemm3x_kernel,
                         cudaFuncAttributeMaxDynamicSharedMemorySize, GSM_TOTAL);
    cudaFuncSetAttribute(flash_hmma,
                         cudaFuncAttributeMaxDynamicSharedMemorySize, FLASH_SMEM);

    rope_table<<<128, 256>>>();
    transpose_qkvw<<<dim3(HD / 32, DD / 32, 10), dim3(32, 8)>>>(qw, kvw);
    convert_split<<<(TOK * DD) / 4 / 256, 256>>>(x);

    // QKV projection + fused rope/scale/split epilogue
    gemm3x_kernel<<<dim3(NQKV / 128, TOK / 128), 256, GSM_TOTAL>>>(nullptr, 0);

    transpose_outw<<<dim3(DD / 32, DD / 32), dim3(32, 8)>>>(ow);

    // HMMA flash attention (writes enc bf16-split into g_Ahi/g_Alo)
    flash_hmma<<<dim3(TT / 64, NHEAD, BB), 256, FLASH_SMEM>>>();

    // Out projection
    gemm3x_kernel<<<dim3(DD / 128, TOK / 128), 256, GSM_TOTAL>>>(out, 1);
}

// round 12
// speedup vs baseline: 1.1083x; 1.1083x over previous
#include <cuda_runtime.h>
#include <cuda_bf16.h>
#include <cuda_fp16.h>
#include <math.h>
#include <stdint.h>

// Problem constants
#define BB 2
#define TT 4096
#define DD 2048
#define NHEAD 8
#define HD 256
#define TOK (BB*TT)           // 8192
#define NQKV 2560             // 8*256 Q + 256 K + 256 V

// ---------------- scratch (device globals; no allocation allowed) ----------
__device__ __nv_bfloat16 g_Qsp[(size_t)2 * TOK * DD];   // 64 MiB (hi | lo)
__device__ __nv_bfloat16 g_Ahi[(size_t)TOK * DD];       // 32 MiB
__device__ __nv_bfloat16 g_Alo[(size_t)TOK * DD];       // 32 MiB
__device__ __nv_bfloat16 g_Bhi[(size_t)NQKV * DD];      // 10 MiB
__device__ __nv_bfloat16 g_Blo[(size_t)NQKV * DD];      // 10 MiB
__device__ __nv_bfloat16 g_Khi[(size_t)TOK * HD];       // 4 MiB
__device__ __nv_bfloat16 g_Klo[(size_t)TOK * HD];       // 4 MiB
__device__ __half        g_Vh [(size_t)TOK * HD];       // 4 MiB
__device__ float2        g_ropetab[(size_t)TT * 128];   // 4 MiB

// =================== ptx helpers ========================
__device__ __forceinline__ uint32_t s2u(const void* p) {
    uint32_t a;
    asm("{ .reg .u64 t; cvta.to.shared.u64 t, %1; cvt.u32.u64 %0, t; }"
        : "=r"(a) : "l"(p));
    return a;
}
__device__ __forceinline__ void cpa16(uint32_t s, const void* g) {
    asm volatile("cp.async.cg.shared.global [%0], [%1], 16;" :: "r"(s), "l"(g));
}
#define CP_COMMIT()  asm volatile("cp.async.commit_group;" ::: "memory")
#define CP_WAIT(N)   asm volatile("cp.async.wait_group %0;" :: "n"(N) : "memory")

#define LDSM4(r0, r1, r2, r3, addr) \
    asm volatile("ldmatrix.sync.aligned.m8n8.x4.shared.b16 {%0,%1,%2,%3}, [%4];" \
                 : "=r"(r0), "=r"(r1), "=r"(r2), "=r"(r3) : "r"(addr))

#define LDSM4T(r0, r1, r2, r3, addr) \
    asm volatile("ldmatrix.sync.aligned.m8n8.x4.trans.shared.b16 {%0,%1,%2,%3}, [%4];" \
                 : "=r"(r0), "=r"(r1), "=r"(r2), "=r"(r3) : "r"(addr))

#define MMA16816(d, a, b0, b1) \
    asm volatile("mma.sync.aligned.m16n8k16.row.col.f32.bf16.bf16.f32 " \
                 "{%0,%1,%2,%3}, {%4,%5,%6,%7}, {%8,%9}, {%0,%1,%2,%3};" \
                 : "+f"((d)[0]), "+f"((d)[1]), "+f"((d)[2]), "+f"((d)[3]) \
                 : "r"((a)[0]), "r"((a)[1]), "r"((a)[2]), "r"((a)[3]), \
                   "r"(b0), "r"(b1))

#define MMAF16(d, a, b0, b1) \
    asm volatile("mma.sync.aligned.m16n8k16.row.col.f32.f16.f16.f32 " \
                 "{%0,%1,%2,%3}, {%4,%5,%6,%7}, {%8,%9}, {%0,%1,%2,%3};" \
                 : "+f"((d)[0]), "+f"((d)[1]), "+f"((d)[2]), "+f"((d)[3]) \
                 : "r"((a)[0]), "r"((a)[1]), "r"((a)[2]), "r"((a)[3]), \
                   "r"(b0), "r"(b1))

// ===========================================================================
// RoPE table
// ===========================================================================
__global__ void rope_table() {
    __shared__ double u1s;
    const int i = blockIdx.x;
    if (threadIdx.x == 0)
        u1s = pow(10000.0, -(double)i / 128.0) * 0.15915494309189533576;
    __syncthreads();
    const double u1 = u1s;
    for (int t = threadIdx.x; t < TT; t += blockDim.x) {
        double u = (double)t * u1;
        float x2 = (float)(2.0 * (u - trunc(u)));
        float s, c;
        sincospif(x2, &s, &c);
        g_ropetab[t * 128 + i] = make_float2(s, c);
    }
}

// ===========================================================================
// Weight prep
// ===========================================================================
__global__ void transpose_qkvw(const float* __restrict__ qw,
                               const float* __restrict__ kvw) {
    __shared__ float t[32][33];
    const int g = blockIdx.z;
    const float* slab = (g < 8) ? qw + (size_t)g * DD * HD
                                : kvw + (size_t)(g - 8) * DD * HD;
    const int h0 = blockIdx.x * 32, k0 = blockIdx.y * 32;
    const int c = threadIdx.x, r0 = threadIdx.y;
#pragma unroll
    for (int i = 0; i < 32; i += 8)
        t[r0 + i][c] = slab[(size_t)(k0 + r0 + i) * HD + h0 + c];
    __syncthreads();
#pragma unroll
    for (int i = 0; i < 32; i += 8) {
        float v = t[c][r0 + i];
        int h = h0 + r0 + i;
        int hp = (g == 9) ? h : ((h < 128) ? 2 * h : 2 * (h - 128) + 1);
        size_t o = (size_t)(g * 256 + hp) * DD + k0 + c;
        __nv_bfloat16 hi = __float2bfloat16(v);
        g_Bhi[o] = hi;
        g_Blo[o] = __float2bfloat16(v - __bfloat162float(hi));
    }
}

__global__ void transpose_outw(const float* __restrict__ ow) {
    __shared__ float t[32][33];
    const int j0 = blockIdx.x * 32, k0 = blockIdx.y * 32;
    const int c = threadIdx.x, r0 = threadIdx.y;
#pragma unroll
    for (int i = 0; i < 32; i += 8)
        t[r0 + i][c] = ow[(size_t)(k0 + r0 + i) * DD + j0 + c];
    __syncthreads();
#pragma unroll
    for (int i = 0; i < 32; i += 8) {
        float v = t[c][r0 + i];
        size_t o = (size_t)(j0 + r0 + i) * DD + k0 + c;
        __nv_bfloat16 hi = __float2bfloat16(v);
        g_Bhi[o] = hi;
        g_Blo[o] = __float2bfloat16(v - __bfloat162float(hi));
    }
}

__global__ void convert_split(const float* __restrict__ src) {
    size_t i = (size_t)blockIdx.x * blockDim.x + threadIdx.x;
    float4 v = ((const float4*)src)[i];
    __nv_bfloat16 hx = __float2bfloat16(v.x), hy = __float2bfloat16(v.y);
    __nv_bfloat16 hz = __float2bfloat16(v.z), hw = __float2bfloat16(v.w);
    __nv_bfloat162* h2 = (__nv_bfloat162*)g_Ahi;
    __nv_bfloat162* l2 = (__nv_bfloat162*)g_Alo;
    h2[2 * i]     = __halves2bfloat162(hx, hy);
    h2[2 * i + 1] = __halves2bfloat162(hz, hw);
    l2[2 * i]     = __halves2bfloat162(
        __float2bfloat16(v.x - __bfloat162float(hx)),
        __float2bfloat16(v.y - __bfloat162float(hy)));
    l2[2 * i + 1] = __halves2bfloat162(
        __float2bfloat16(v.z - __bfloat162float(hz)),
        __float2bfloat16(v.w - __bfloat162float(hw)));
}

// ===========================================================================
// HMMA 3xBF16 GEMM — 2-stage ring, 2 CTAs/SM (regs <= 128 via transient
// A-fragments + launch_bounds(256,2)).
// ===========================================================================
#define KC 32
#define TROW 80
#define TILEB (128 * TROW)
#define STAGEB (4 * TILEB)          // 40960
#define GSM_TOTAL (2 * STAGEB)      // 81920; x2 CTAs = 160KB <= 228KB

__device__ __forceinline__ void load_stage(uint32_t smb, int s, int k0, int tid,
                                           const __nv_bfloat16* const* base) {
    uint32_t sb = smb + s * STAGEB;
#pragma unroll
    for (int j = 0; j < 8; ++j) {
        int c = tid + j * 256;
        const int tile = j >> 1;
        int inner = c & 511;
        int row = inner >> 2, seg = inner & 3;
        const __nv_bfloat16* gp = base[tile] + (size_t)row * DD + k0 + seg * 8;
        cpa16(sb + tile * TILEB + row * TROW + seg * 16, gp);
    }
    CP_COMMIT();
}

__global__ __launch_bounds__(256, 2) void gemm3x_kernel(float* outp, int mode) {
    extern __shared__ __align__(128) char sm[];
    uint32_t smb = s2u(sm);
    const int tid = threadIdx.x;
    const int lane = tid & 31, wid = tid >> 5;
    const int wm = wid & 1, wn = wid >> 1;
    const int n0 = blockIdx.x * 128;
    const int m0 = blockIdx.y * 128;

    const __nv_bfloat16* base[4] = {
        g_Ahi + (size_t)m0 * DD, g_Alo + (size_t)m0 * DD,
        g_Bhi + (size_t)n0 * DD, g_Blo + (size_t)n0 * DD };

    float acc[4][4][4];
#pragma unroll
    for (int i = 0; i < 4; ++i)
#pragma unroll
        for (int j = 0; j < 4; ++j)
#pragma unroll
            for (int r = 0; r < 4; ++r) acc[i][j][r] = 0.f;

    const uint32_t a_off = (uint32_t)((wm * 64 + (lane & 15)) * TROW
                                      + (lane >> 4) * 16);
    const uint32_t b_off = (uint32_t)((wn * 32 + (lane >> 4) * 8 + (lane & 7)) * TROW
                                      + ((lane >> 3) & 1) * 16);

    load_stage(smb, 0, 0, tid, base);

    const int NIT = DD / KC;   // 64
    for (int it = 0; it < NIT; ++it) {
        const int s = it & 1;
        if (it + 1 < NIT) {
            load_stage(smb, s ^ 1, (it + 1) * KC, tid, base);
            CP_WAIT(1);
        } else {
            CP_WAIT(0);
        }
        __syncthreads();

        const uint32_t st = smb + s * STAGEB;
#pragma unroll
        for (int ks = 0; ks < 2; ++ks) {
            const uint32_t ko = ks * 32;
            // B fragments for the whole 32-col strip (live: 16 regs)
            uint32_t bhi[4][2], blo[4][2];
#pragma unroll
            for (int pr = 0; pr < 2; ++pr) {
                uint32_t ba = st + 2 * TILEB + b_off + pr * (16 * TROW) + ko;
                LDSM4(bhi[2 * pr][0], bhi[2 * pr][1],
                      bhi[2 * pr + 1][0], bhi[2 * pr + 1][1], ba);
                LDSM4(blo[2 * pr][0], blo[2 * pr][1],
                      blo[2 * pr + 1][0], blo[2 * pr + 1][1], ba + TILEB);
            }
            // A fragments transient per mf (8 regs), fire 12 MMAs immediately
#pragma unroll
            for (int mf = 0; mf < 4; ++mf) {
                uint32_t ahi[4], alo[4];
                uint32_t aa = st + a_off + mf * (16 * TROW) + ko;
                LDSM4(ahi[0], ahi[1], ahi[2], ahi[3], aa);
                LDSM4(alo[0], alo[1], alo[2], alo[3], aa + TILEB);
#pragma unroll
                for (int nf = 0; nf < 4; ++nf) {
                    MMA16816(acc[mf][nf], ahi, bhi[nf][0], bhi[nf][1]);
                    MMA16816(acc[mf][nf], ahi, blo[nf][0], blo[nf][1]);
                    MMA16816(acc[mf][nf], alo, bhi[nf][0], bhi[nf][1]);
                }
            }
        }
        __syncthreads();
    }

    const int r0 = m0 + wm * 64 + (lane >> 2);
    const int lc0 = wn * 32 + 2 * (lane & 3);

    if (mode == 1) {
        const int c0 = n0 + lc0;
#pragma unroll
        for (int mf = 0; mf < 4; ++mf)
#pragma unroll
            for (int nf = 0; nf < 4; ++nf) {
                float* p0 = outp + (size_t)(r0 + mf * 16) * DD + c0 + nf * 8;
                *(float2*)p0 = make_float2(acc[mf][nf][0], acc[mf][nf][1]);
                float* p1 = p0 + 8 * DD;
                *(float2*)p1 = make_float2(acc[mf][nf][2], acc[mf][nf][3]);
            }
    } else if (n0 < 2048) {
        __nv_bfloat16* Qhi = g_Qsp;
        __nv_bfloat16* Qlo = g_Qsp + (size_t)TOK * DD;
#pragma unroll
        for (int mf = 0; mf < 4; ++mf)
#pragma unroll
            for (int nf = 0; nf < 4; ++nf) {
                int row1 = r0 + mf * 16, row2 = row1 + 8;
                int col = n0 + lc0 + nf * 8;
                int ri = (col & 255) >> 1;
                float2 sc1 = g_ropetab[(row1 & (TT - 1)) * 128 + ri];
                float2 sc2 = g_ropetab[(row2 & (TT - 1)) * 128 + ri];
                float a1 = acc[mf][nf][0], b1 = acc[mf][nf][1];
                float a2 = acc[mf][nf][2], b2 = acc[mf][nf][3];
                float x1 = (a1 * sc1.y - b1 * sc1.x) * 0.0625f;
                float y1 = (b1 * sc1.y + a1 * sc1.x) * 0.0625f;
                float x2 = (a2 * sc2.y - b2 * sc2.x) * 0.0625f;
                float y2 = (b2 * sc2.y + a2 * sc2.x) * 0.0625f;
                __nv_bfloat16 hx1 = __float2bfloat16(x1), hy1 = __float2bfloat16(y1);
                __nv_bfloat16 hx2 = __float2bfloat16(x2), hy2 = __float2bfloat16(y2);
                *(__nv_bfloat162*)&Qhi[(size_t)row1 * DD + col] = __halves2bfloat162(hx1, hy1);
                *(__nv_bfloat162*)&Qhi[(size_t)row2 * DD + col] = __halves2bfloat162(hx2, hy2);
                *(__nv_bfloat162*)&Qlo[(size_t)row1 * DD + col] = __halves2bfloat162(
                    __float2bfloat16(x1 - __bfloat162float(hx1)),
                    __float2bfloat16(y1 - __bfloat162float(hy1)));
                *(__nv_bfloat162*)&Qlo[(size_t)row2 * DD + col] = __halves2bfloat162(
                    __float2bfloat16(x2 - __bfloat162float(hx2)),
                    __float2bfloat16(y2 - __bfloat162float(hy2)));
            }
    } else if (n0 < 2304) {
#pragma unroll
        for (int mf = 0; mf < 4; ++mf)
#pragma unroll
            for (int nf = 0; nf < 4; ++nf) {
                int row1 = r0 + mf * 16, row2 = row1 + 8;
                int col = (n0 - 2048) + lc0 + nf * 8;
                int ri = col >> 1;
                float2 sc1 = g_ropetab[(row1 & (TT - 1)) * 128 + ri];
                float2 sc2 = g_ropetab[(row2 & (TT - 1)) * 128 + ri];
                float a1 = acc[mf][nf][0], b1 = acc[mf][nf][1];
                float a2 = acc[mf][nf][2], b2 = acc[mf][nf][3];
                float x1 = a1 * sc1.y - b1 * sc1.x;
                float y1 = b1 * sc1.y + a1 * sc1.x;
                float x2 = a2 * sc2.y - b2 * sc2.x;
                float y2 = b2 * sc2.y + a2 * sc2.x;
                __nv_bfloat16 hx1 = __float2bfloat16(x1), hy1 = __float2bfloat16(y1);
                __nv_bfloat16 hx2 = __float2bfloat16(x2), hy2 = __float2bfloat16(y2);
                *(__nv_bfloat162*)&g_Khi[(size_t)row1 * HD + col] = __halves2bfloat162(hx1, hy1);
                *(__nv_bfloat162*)&g_Khi[(size_t)row2 * HD + col] = __halves2bfloat162(hx2, hy2);
                *(__nv_bfloat162*)&g_Klo[(size_t)row1 * HD + col] = __halves2bfloat162(
                    __float2bfloat16(x1 - __bfloat162float(hx1)),
                    __float2bfloat16(y1 - __bfloat162float(hy1)));
                *(__nv_bfloat162*)&g_Klo[(size_t)row2 * HD + col] = __halves2bfloat162(
                    __float2bfloat16(x2 - __bfloat162float(hx2)),
                    __float2bfloat16(y2 - __bfloat162float(hy2)));
            }
    } else {
#pragma unroll
        for (int mf = 0; mf < 4; ++mf)
#pragma unroll
            for (int nf = 0; nf < 4; ++nf) {
                int row1 = r0 + mf * 16, row2 = row1 + 8;
                int col = (n0 - 2304) + lc0 + nf * 8;
                *(__half2*)&g_Vh[(size_t)row1 * HD + col] =
                    __floats2half2_rn(acc[mf][nf][0], acc[mf][nf][1]);
                *(__half2*)&g_Vh[(size_t)row2 * HD + col] =
                    __floats2half2_rn(acc[mf][nf][2], acc[mf][nf][3]);
            }
    }
}

// ===========================================================================
// HMMA causal flash attention — 3-stage K/V ring (unchanged from R11)
// ===========================================================================
#define BN 32
#define KST 528
#define PST 80
#define FSTAGE 50688
#define ST_KHI(s) ((s)*FSTAGE)
#define ST_KLO(s) (ST_KHI(s)+16896)
#define ST_VH(s)  (ST_KHI(s)+33792)
#define SQLO   (3*FSTAGE)               // 152064
#define SPHI   (SQLO + 33792)           // 185856
#define SRED   (SPHI + 64*PST)          // 190976
#define FLASH_SMEM (SRED + 1024)        // 192000

__device__ __forceinline__ void flash_load(uint32_t smb, int s, int s0, int tid,
                                           const __nv_bfloat16* kh,
                                           const __nv_bfloat16* kl,
                                           const __half* vh) {
#pragma unroll
    for (int i2 = 0; i2 < 4; ++i2) {
        int c = tid + i2 * 256;
        int row = c >> 5, seg = c & 31;
        size_t go = (size_t)(s0 + row) * 512 + seg * 16;
        uint32_t so = row * KST + seg * 16;
        cpa16(smb + ST_KHI(s) + so, (const char*)kh + go);
        cpa16(smb + ST_KLO(s) + so, (const char*)kl + go);
        cpa16(smb + ST_VH(s)  + so, (const char*)vh + go);
    }
    CP_COMMIT();
}

__global__ __launch_bounds__(256) void flash_hmma() {
    extern __shared__ __align__(128) char sm[];
    uint32_t smb = s2u(sm);
    const int tid = threadIdx.x, lane = tid & 31, wid = tid >> 5;
    const int wm = wid >> 1, wn = wid & 1;
    const int bx = gridDim.x - 1 - blockIdx.x;
    const int n = blockIdx.y, b = blockIdx.z;
    const int q0 = bx * 64;
    const size_t tb = (size_t)b * TT;

    const char* qh_g = (const char*)(g_Qsp + (size_t)(tb + q0) * DD + n * 256);
    const char* ql_g = (const char*)(g_Qsp + (size_t)TOK * DD
                                     + (size_t)(tb + q0) * DD + n * 256);
    const __nv_bfloat16* kh_g = g_Khi + tb * 256;
    const __nv_bfloat16* kl_g = g_Klo + tb * 256;
    const __half* vh_g = g_Vh + tb * 256;

#pragma unroll
    for (int i2 = 0; i2 < 8; ++i2) {
        int c = tid + i2 * 256;
        int row = c >> 5, seg = c & 31;
        cpa16(smb + ST_KHI(2) + row * KST + seg * 16, qh_g + (size_t)row * 4096 + seg * 16);
        cpa16(smb + SQLO + row * KST + seg * 16,      ql_g + (size_t)row * 4096 + seg * 16);
    }
    CP_COMMIT();
    CP_WAIT(0);
    __syncthreads();

    const uint32_t a_base = (uint32_t)((wm * 16 + (lane & 15)) * KST + (lane >> 4) * 16);
    uint32_t qh[16][4];
#pragma unroll
    for (int ks = 0; ks < 16; ++ks)
        LDSM4(qh[ks][0], qh[ks][1], qh[ks][2], qh[ks][3],
              smb + ST_KHI(2) + a_base + ks * 32);
    __syncthreads();

    const int ntiles = 2 * bx + 2;
    flash_load(smb, 0, 0, tid, kh_g, kl_g, vh_g);
    if (ntiles > 1) flash_load(smb, 1, BN, tid, kh_g, kl_g, vh_g);

    float o[16][4];
#pragma unroll
    for (int nf = 0; nf < 16; ++nf)
#pragma unroll
        for (int r = 0; r < 4; ++r) o[nf][r] = 0.f;
    float m1 = -1e30f, m2 = -1e30f, l1 = 0.f, l2 = 0.f;

    const int grow1 = wm * 16 + (lane >> 2);
    const int grow2 = grow1 + 8;
    const int ccol = 2 * (lane & 3);
    float* rmaxs = (float*)(sm + SRED);
    float* rsums = (float*)(sm + SRED + 512);
    const uint32_t b_base = (uint32_t)((wn * 16 + ((lane >> 4) << 3) + (lane & 7)) * KST
                                       + ((lane >> 3) & 1) * 16);
    const uint32_t p_base = (uint32_t)((wm * 16 + (lane & 15)) * PST + (lane >> 4) * 16);
    const uint32_t v_base = (uint32_t)((lane & 15) * KST + wn * 256 + (lane >> 4) * 16);

    int s = 0;
    for (int kt = 0; kt < ntiles; ++kt) {
        if (kt == ntiles - 1) { CP_WAIT(0); } else { CP_WAIT(1); }
        __syncthreads();
        if (kt + 2 < ntiles)
            flash_load(smb, (s + 2 >= 3) ? s - 1 : s + 2, (kt + 2) * BN,
                       tid, kh_g, kl_g, vh_g);

        float sa[2][4];
#pragma unroll
        for (int nf = 0; nf < 2; ++nf)
#pragma unroll
            for (int r = 0; r < 4; ++r) sa[nf][r] = 0.f;
#pragma unroll
        for (int ks = 0; ks < 16; ++ks) {
            uint32_t ql[4];
            LDSM4(ql[0], ql[1], ql[2], ql[3], smb + SQLO + a_base + ks * 32);
            uint32_t bh0, bh1, bh2, bh3, bl0, bl1, bl2, bl3;
            LDSM4(bh0, bh1, bh2, bh3, smb + ST_KHI(s) + b_base + ks * 32);
            LDSM4(bl0, bl1, bl2, bl3, smb + ST_KLO(s) + b_base + ks * 32);
            MMA16816(sa[0], qh[ks], bh0, bh1);
            MMA16816(sa[1], qh[ks], bh2, bh3);
            MMA16816(sa[0], qh[ks], bl0, bl1);
            MMA16816(sa[1], qh[ks], bl2, bl3);
            MMA16816(sa[0], ql, bh0, bh1);
            MMA16816(sa[1], ql, bh2, bh3);
        }

        const int s0 = kt * BN;
        if (kt >= 2 * bx) {
            const int qr1 = q0 + grow1, qr2 = q0 + grow2;
#pragma unroll
            for (int nf = 0; nf < 2; ++nf) {
                int c0 = s0 + wn * 16 + nf * 8 + ccol;
                if (c0     > qr1) sa[nf][0] = -1e30f;
                if (c0 + 1 > qr1) sa[nf][1] = -1e30f;
                if (c0     > qr2) sa[nf][2] = -1e30f;
                if (c0 + 1 > qr2) sa[nf][3] = -1e30f;
            }
        }

        float pm1 = fmaxf(fmaxf(sa[0][0], sa[0][1]), fmaxf(sa[1][0], sa[1][1]));
        float pm2 = fmaxf(fmaxf(sa[0][2], sa[0][3]), fmaxf(sa[1][2], sa[1][3]));
        pm1 = fmaxf(pm1, __shfl_xor_sync(0xffffffffu, pm1, 1));
        pm1 = fmaxf(pm1, __shfl_xor_sync(0xffffffffu, pm1, 2));
        pm2 = fmaxf(pm2, __shfl_xor_sync(0xffffffffu, pm2, 1));
        pm2 = fmaxf(pm2, __shfl_xor_sync(0xffffffffu, pm2, 2));
        if ((lane & 3) == 0) {
            rmaxs[wn * 64 + grow1] = pm1;
            rmaxs[wn * 64 + grow2] = pm2;
        }
        __syncthreads();
        float mn1 = fmaxf(m1, fmaxf(rmaxs[grow1], rmaxs[64 + grow1]));
        float mn2 = fmaxf(m2, fmaxf(rmaxs[grow2], rmaxs[64 + grow2]));
        float al1 = __expf(m1 - mn1), al2 = __expf(m2 - mn2);
        m1 = mn1; m2 = mn2;

        float ps1 = 0.f, ps2 = 0.f;
#pragma unroll
        for (int nf = 0; nf < 2; ++nf) {
            float e0 = __expf(sa[nf][0] - mn1), e1 = __expf(sa[nf][1] - mn1);
            float e2 = __expf(sa[nf][2] - mn2), e3 = __expf(sa[nf][3] - mn2);
            ps1 += e0 + e1; ps2 += e2 + e3;
            int colB = (wn * 16 + nf * 8 + ccol) * 2;
            *(__half2*)(sm + SPHI + grow1 * PST + colB) = __floats2half2_rn(e0, e1);
            *(__half2*)(sm + SPHI + grow2 * PST + colB) = __floats2half2_rn(e2, e3);
        }
        ps1 += __shfl_xor_sync(0xffffffffu, ps1, 1);
        ps1 += __shfl_xor_sync(0xffffffffu, ps1, 2);
        ps2 += __shfl_xor_sync(0xffffffffu, ps2, 1);
        ps2 += __shfl_xor_sync(0xffffffffu, ps2, 2);
        if ((lane & 3) == 0) {
            rsums[wn * 64 + grow1] = ps1;
            rsums[wn * 64 + grow2] = ps2;
        }
#pragma unroll
        for (int nf = 0; nf < 16; ++nf) {
            o[nf][0] *= al1; o[nf][1] *= al1;
            o[nf][2] *= al2; o[nf][3] *= al2;
        }
        __syncthreads();
        l1 = l1 * al1 + rsums[grow1] + rsums[64 + grow1];
        l2 = l2 * al2 + rsums[grow2] + rsums[64 + grow2];

#pragma unroll
        for (int ks = 0; ks < 2; ++ks) {
            uint32_t ph[4];
            LDSM4(ph[0], ph[1], ph[2], ph[3], smb + SPHI + p_base + ks * 32);
#pragma unroll
            for (int nb = 0; nb < 8; ++nb) {
                uint32_t v0, v1, v2, v3;
                LDSM4T(v0, v1, v2, v3,
                       smb + ST_VH(s) + v_base + ks * (16 * KST) + nb * 32);
                MMAF16(o[2 * nb],     ph, v0, v1);
                MMAF16(o[2 * nb + 1], ph, v2, v3);
            }
        }
        s = (s == 2) ? 0 : s + 1;
    }

    float i1 = 1.f / l1, i2 = 1.f / l2;
#pragma unroll
    for (int nf = 0; nf < 16; ++nf) {
        int col = n * 256 + wn * 128 + nf * 8 + ccol;
        size_t o1 = (tb + q0 + grow1) * (size_t)DD + col;
        size_t o2 = (tb + q0 + grow2) * (size_t)DD + col;
        float v0 = o[nf][0] * i1, v1 = o[nf][1] * i1;
        float v2 = o[nf][2] * i2, v3 = o[nf][3] * i2;
        __nv_bfloat16 h0 = __float2bfloat16(v0), h1 = __float2bfloat16(v1);
        __nv_bfloat16 h2 = __float2bfloat16(v2), h3 = __float2bfloat16(v3);
        *(__nv_bfloat162*)&g_Ahi[o1] = __halves2bfloat162(h0, h1);
        *(__nv_bfloat162*)&g_Ahi[o2] = __halves2bfloat162(h2, h3);
        *(__nv_bfloat162*)&g_Alo[o1] = __halves2bfloat162(
            __float2bfloat16(v0 - __bfloat162float(h0)),
            __float2bfloat16(v1 - __bfloat162float(h1)));
        *(__nv_bfloat162*)&g_Alo[o2] = __halves2bfloat162(
            __float2bfloat16(v2 - __bfloat162float(h2)),
            __float2bfloat16(v3 - __bfloat162float(h3)));
    }
}

// ===========================================================================
// launch — inputs: 0=x, 1=segment_pos, 2=attn_mask, 3=q_w, 4=kv_w, 5=out_w
// ===========================================================================
extern "C" void kernel_launch(void* const* d_in, const int* in_sizes, int n_in,
                              void* d_out, int out_size) {
    (void)in_sizes; (void)n_in; (void)out_size;
    const float* x   = (const float*)d_in[0];
    const float* qw  = (const float*)d_in[3];
    const float* kvw = (const float*)d_in[4];
    const float* ow  = (const float*)d_in[5];
    float* out = (float*)d_out;

    cudaFuncSetAttribute(gemm3x_kernel,
                         cudaFuncAttributeMaxDynamicSharedMemorySize, GSM_TOTAL);
    cudaFuncSetAttribute(flash_hmma,
                         cudaFuncAttributeMaxDynamicSharedMemorySize, FLASH_SMEM);

    rope_table<<<128, 256>>>();
    transpose_qkvw<<<dim3(HD / 32, DD / 32, 10), dim3(32, 8)>>>(qw, kvw);
    convert_split<<<(TOK * DD) / 4 / 256, 256>>>(x);

    // QKV projection + fused rope/scale/split epilogue
    gemm3x_kernel<<<dim3(NQKV / 128, TOK / 128), 256, GSM_TOTAL>>>(nullptr, 0);

    transpose_outw<<<dim3(DD / 32, DD / 32), dim3(32, 8)>>>(ow);

    // HMMA flash attention (writes enc bf16-split into g_Ahi/g_Alo)
    flash_hmma<<<dim3(TT / 64, NHEAD, BB), 256, FLASH_SMEM>>>();

    // Out projection
    gemm3x_kernel<<<dim3(DD / 128, TOK / 128), 256, GSM_TOTAL>>>(out, 1);
}

// round 13
// speedup vs baseline: 1.2081x; 1.0900x over previous
#include <cuda_runtime.h>
#include <cuda_bf16.h>
#include <cuda_fp16.h>
#include <math.h>
#include <stdint.h>

// Problem constants
#define BB 2
#define TT 4096
#define DD 2048
#define NHEAD 8
#define HD 256
#define TOK (BB*TT)           // 8192
#define NQKV 2560             // 8*256 Q + 256 K + 256 V

// ---------------- scratch (device globals; no allocation allowed) ----------
__device__ __nv_bfloat16 g_Qsp[(size_t)2 * TOK * DD];   // 64 MiB (hi | lo)
__device__ __nv_bfloat16 g_Ahi[(size_t)TOK * DD];       // 32 MiB
__device__ __nv_bfloat16 g_Alo[(size_t)TOK * DD];       // 32 MiB
__device__ __nv_bfloat16 g_Bhi[(size_t)NQKV * DD];      // 10 MiB
__device__ __nv_bfloat16 g_Blo[(size_t)NQKV * DD];      // 10 MiB
__device__ __nv_bfloat16 g_Khi[(size_t)TOK * HD];       // 4 MiB
__device__ __nv_bfloat16 g_Klo[(size_t)TOK * HD];       // 4 MiB
__device__ __half        g_Vh [(size_t)TOK * HD];       // 4 MiB
__device__ float2        g_ropetab[(size_t)TT * 128];   // 4 MiB

// =================== ptx helpers ========================
__device__ __forceinline__ uint32_t s2u(const void* p) {
    uint32_t a;
    asm("{ .reg .u64 t; cvta.to.shared.u64 t, %1; cvt.u32.u64 %0, t; }"
        : "=r"(a) : "l"(p));
    return a;
}
__device__ __forceinline__ void cpa16(uint32_t s, const void* g) {
    asm volatile("cp.async.cg.shared.global [%0], [%1], 16;" :: "r"(s), "l"(g));
}
#define CP_COMMIT()  asm volatile("cp.async.commit_group;" ::: "memory")
#define CP_WAIT(N)   asm volatile("cp.async.wait_group %0;" :: "n"(N) : "memory")

#define LDSM4(r0, r1, r2, r3, addr) \
    asm volatile("ldmatrix.sync.aligned.m8n8.x4.shared.b16 {%0,%1,%2,%3}, [%4];" \
                 : "=r"(r0), "=r"(r1), "=r"(r2), "=r"(r3) : "r"(addr))

#define LDSM4T(r0, r1, r2, r3, addr) \
    asm volatile("ldmatrix.sync.aligned.m8n8.x4.trans.shared.b16 {%0,%1,%2,%3}, [%4];" \
                 : "=r"(r0), "=r"(r1), "=r"(r2), "=r"(r3) : "r"(addr))

#define MMA16816(d, a, b0, b1) \
    asm volatile("mma.sync.aligned.m16n8k16.row.col.f32.bf16.bf16.f32 " \
                 "{%0,%1,%2,%3}, {%4,%5,%6,%7}, {%8,%9}, {%0,%1,%2,%3};" \
                 : "+f"((d)[0]), "+f"((d)[1]), "+f"((d)[2]), "+f"((d)[3]) \
                 : "r"((a)[0]), "r"((a)[1]), "r"((a)[2]), "r"((a)[3]), \
                   "r"(b0), "r"(b1))

#define MMAF16(d, a, b0, b1) \
    asm volatile("mma.sync.aligned.m16n8k16.row.col.f32.f16.f16.f32 " \
                 "{%0,%1,%2,%3}, {%4,%5,%6,%7}, {%8,%9}, {%0,%1,%2,%3};" \
                 : "+f"((d)[0]), "+f"((d)[1]), "+f"((d)[2]), "+f"((d)[3]) \
                 : "r"((a)[0]), "r"((a)[1]), "r"((a)[2]), "r"((a)[3]), \
                   "r"(b0), "r"(b1))

// ===========================================================================
// RoPE table
// ===========================================================================
__global__ void rope_table() {
    __shared__ double u1s;
    const int i = blockIdx.x;
    if (threadIdx.x == 0)
        u1s = pow(10000.0, -(double)i / 128.0) * 0.15915494309189533576;
    __syncthreads();
    const double u1 = u1s;
    for (int t = threadIdx.x; t < TT; t += blockDim.x) {
        double u = (double)t * u1;
        float x2 = (float)(2.0 * (u - trunc(u)));
        float s, c;
        sincospif(x2, &s, &c);
        g_ropetab[t * 128 + i] = make_float2(s, c);
    }
}

// ===========================================================================
// Weight prep (unchanged)
// ===========================================================================
__global__ void transpose_qkvw(const float* __restrict__ qw,
                               const float* __restrict__ kvw) {
    __shared__ float t[32][33];
    const int g = blockIdx.z;
    const float* slab = (g < 8) ? qw + (size_t)g * DD * HD
                                : kvw + (size_t)(g - 8) * DD * HD;
    const int h0 = blockIdx.x * 32, k0 = blockIdx.y * 32;
    const int c = threadIdx.x, r0 = threadIdx.y;
#pragma unroll
    for (int i = 0; i < 32; i += 8)
        t[r0 + i][c] = slab[(size_t)(k0 + r0 + i) * HD + h0 + c];
    __syncthreads();
#pragma unroll
    for (int i = 0; i < 32; i += 8) {
        float v = t[c][r0 + i];
        int h = h0 + r0 + i;
        int hp = (g == 9) ? h : ((h < 128) ? 2 * h : 2 * (h - 128) + 1);
        size_t o = (size_t)(g * 256 + hp) * DD + k0 + c;
        __nv_bfloat16 hi = __float2bfloat16(v);
        g_Bhi[o] = hi;
        g_Blo[o] = __float2bfloat16(v - __bfloat162float(hi));
    }
}

__global__ void transpose_outw(const float* __restrict__ ow) {
    __shared__ float t[32][33];
    const int j0 = blockIdx.x * 32, k0 = blockIdx.y * 32;
    const int c = threadIdx.x, r0 = threadIdx.y;
#pragma unroll
    for (int i = 0; i < 32; i += 8)
        t[r0 + i][c] = ow[(size_t)(k0 + r0 + i) * DD + j0 + c];
    __syncthreads();
#pragma unroll
    for (int i = 0; i < 32; i += 8) {
        float v = t[c][r0 + i];
        size_t o = (size_t)(j0 + r0 + i) * DD + k0 + c;
        __nv_bfloat16 hi = __float2bfloat16(v);
        g_Bhi[o] = hi;
        g_Blo[o] = __float2bfloat16(v - __bfloat162float(hi));
    }
}

__global__ void convert_split(const float* __restrict__ src) {
    size_t i = (size_t)blockIdx.x * blockDim.x + threadIdx.x;
    float4 v = ((const float4*)src)[i];
    __nv_bfloat16 hx = __float2bfloat16(v.x), hy = __float2bfloat16(v.y);
    __nv_bfloat16 hz = __float2bfloat16(v.z), hw = __float2bfloat16(v.w);
    __nv_bfloat162* h2 = (__nv_bfloat162*)g_Ahi;
    __nv_bfloat162* l2 = (__nv_bfloat162*)g_Alo;
    h2[2 * i]     = __halves2bfloat162(hx, hy);
    h2[2 * i + 1] = __halves2bfloat162(hz, hw);
    l2[2 * i]     = __halves2bfloat162(
        __float2bfloat16(v.x - __bfloat162float(hx)),
        __float2bfloat16(v.y - __bfloat162float(hy)));
    l2[2 * i + 1] = __halves2bfloat162(
        __float2bfloat16(v.z - __bfloat162float(hz)),
        __float2bfloat16(v.w - __bfloat162float(hw)));
}

// ===========================================================================
// HMMA 3xBF16 GEMM — 2-stage ring, 2 CTAs/SM (R12 winner, unchanged)
// ===========================================================================
#define KC 32
#define TROW 80
#define TILEB (128 * TROW)
#define STAGEB (4 * TILEB)
#define GSM_TOTAL (2 * STAGEB)

__device__ __forceinline__ void load_stage(uint32_t smb, int s, int k0, int tid,
                                           const __nv_bfloat16* const* base) {
    uint32_t sb = smb + s * STAGEB;
#pragma unroll
    for (int j = 0; j < 8; ++j) {
        int c = tid + j * 256;
        const int tile = j >> 1;
        int inner = c & 511;
        int row = inner >> 2, seg = inner & 3;
        const __nv_bfloat16* gp = base[tile] + (size_t)row * DD + k0 + seg * 8;
        cpa16(sb + tile * TILEB + row * TROW + seg * 16, gp);
    }
    CP_COMMIT();
}

__global__ __launch_bounds__(256, 2) void gemm3x_kernel(float* outp, int mode) {
    extern __shared__ __align__(128) char sm[];
    uint32_t smb = s2u(sm);
    const int tid = threadIdx.x;
    const int lane = tid & 31, wid = tid >> 5;
    const int wm = wid & 1, wn = wid >> 1;
    const int n0 = blockIdx.x * 128;
    const int m0 = blockIdx.y * 128;

    const __nv_bfloat16* base[4] = {
        g_Ahi + (size_t)m0 * DD, g_Alo + (size_t)m0 * DD,
        g_Bhi + (size_t)n0 * DD, g_Blo + (size_t)n0 * DD };

    float acc[4][4][4];
#pragma unroll
    for (int i = 0; i < 4; ++i)
#pragma unroll
        for (int j = 0; j < 4; ++j)
#pragma unroll
            for (int r = 0; r < 4; ++r) acc[i][j][r] = 0.f;

    const uint32_t a_off = (uint32_t)((wm * 64 + (lane & 15)) * TROW
                                      + (lane >> 4) * 16);
    const uint32_t b_off = (uint32_t)((wn * 32 + (lane >> 4) * 8 + (lane & 7)) * TROW
                                      + ((lane >> 3) & 1) * 16);

    load_stage(smb, 0, 0, tid, base);

    const int NIT = DD / KC;
    for (int it = 0; it < NIT; ++it) {
        const int s = it & 1;
        if (it + 1 < NIT) {
            load_stage(smb, s ^ 1, (it + 1) * KC, tid, base);
            CP_WAIT(1);
        } else {
            CP_WAIT(0);
        }
        __syncthreads();

        const uint32_t st = smb + s * STAGEB;
#pragma unroll
        for (int ks = 0; ks < 2; ++ks) {
            const uint32_t ko = ks * 32;
            uint32_t bhi[4][2], blo[4][2];
#pragma unroll
            for (int pr = 0; pr < 2; ++pr) {
                uint32_t ba = st + 2 * TILEB + b_off + pr * (16 * TROW) + ko;
                LDSM4(bhi[2 * pr][0], bhi[2 * pr][1],
                      bhi[2 * pr + 1][0], bhi[2 * pr + 1][1], ba);
                LDSM4(blo[2 * pr][0], blo[2 * pr][1],
                      blo[2 * pr + 1][0], blo[2 * pr + 1][1], ba + TILEB);
            }
#pragma unroll
            for (int mf = 0; mf < 4; ++mf) {
                uint32_t ahi[4], alo[4];
                uint32_t aa = st + a_off + mf * (16 * TROW) + ko;
                LDSM4(ahi[0], ahi[1], ahi[2], ahi[3], aa);
                LDSM4(alo[0], alo[1], alo[2], alo[3], aa + TILEB);
#pragma unroll
                for (int nf = 0; nf < 4; ++nf) {
                    MMA16816(acc[mf][nf], ahi, bhi[nf][0], bhi[nf][1]);
                    MMA16816(acc[mf][nf], ahi, blo[nf][0], blo[nf][1]);
                    MMA16816(acc[mf][nf], alo, bhi[nf][0], bhi[nf][1]);
                }
            }
        }
        __syncthreads();
    }

    const int r0 = m0 + wm * 64 + (lane >> 2);
    const int lc0 = wn * 32 + 2 * (lane & 3);

    if (mode == 1) {
        const int c0 = n0 + lc0;
#pragma unroll
        for (int mf = 0; mf < 4; ++mf)
#pragma unroll
            for (int nf = 0; nf < 4; ++nf) {
                float* p0 = outp + (size_t)(r0 + mf * 16) * DD + c0 + nf * 8;
                *(float2*)p0 = make_float2(acc[mf][nf][0], acc[mf][nf][1]);
                float* p1 = p0 + 8 * DD;
                *(float2*)p1 = make_float2(acc[mf][nf][2], acc[mf][nf][3]);
            }
    } else if (n0 < 2048) {
        __nv_bfloat16* Qhi = g_Qsp;
        __nv_bfloat16* Qlo = g_Qsp + (size_t)TOK * DD;
#pragma unroll
        for (int mf = 0; mf < 4; ++mf)
#pragma unroll
            for (int nf = 0; nf < 4; ++nf) {
                int row1 = r0 + mf * 16, row2 = row1 + 8;
                int col = n0 + lc0 + nf * 8;
                int ri = (col & 255) >> 1;
                float2 sc1 = g_ropetab[(row1 & (TT - 1)) * 128 + ri];
                float2 sc2 = g_ropetab[(row2 & (TT - 1)) * 128 + ri];
                float a1 = acc[mf][nf][0], b1 = acc[mf][nf][1];
                float a2 = acc[mf][nf][2], b2 = acc[mf][nf][3];
                float x1 = (a1 * sc1.y - b1 * sc1.x) * 0.0625f;
                float y1 = (b1 * sc1.y + a1 * sc1.x) * 0.0625f;
                float x2 = (a2 * sc2.y - b2 * sc2.x) * 0.0625f;
                float y2 = (b2 * sc2.y + a2 * sc2.x) * 0.0625f;
                __nv_bfloat16 hx1 = __float2bfloat16(x1), hy1 = __float2bfloat16(y1);
                __nv_bfloat16 hx2 = __float2bfloat16(x2), hy2 = __float2bfloat16(y2);
                *(__nv_bfloat162*)&Qhi[(size_t)row1 * DD + col] = __halves2bfloat162(hx1, hy1);
                *(__nv_bfloat162*)&Qhi[(size_t)row2 * DD + col] = __halves2bfloat162(hx2, hy2);
                *(__nv_bfloat162*)&Qlo[(size_t)row1 * DD + col] = __halves2bfloat162(
                    __float2bfloat16(x1 - __bfloat162float(hx1)),
                    __float2bfloat16(y1 - __bfloat162float(hy1)));
                *(__nv_bfloat162*)&Qlo[(size_t)row2 * DD + col] = __halves2bfloat162(
                    __float2bfloat16(x2 - __bfloat162float(hx2)),
                    __float2bfloat16(y2 - __bfloat162float(hy2)));
            }
    } else if (n0 < 2304) {
#pragma unroll
        for (int mf = 0; mf < 4; ++mf)
#pragma unroll
            for (int nf = 0; nf < 4; ++nf) {
                int row1 = r0 + mf * 16, row2 = row1 + 8;
                int col = (n0 - 2048) + lc0 + nf * 8;
                int ri = col >> 1;
                float2 sc1 = g_ropetab[(row1 & (TT - 1)) * 128 + ri];
                float2 sc2 = g_ropetab[(row2 & (TT - 1)) * 128 + ri];
                float a1 = acc[mf][nf][0], b1 = acc[mf][nf][1];
                float a2 = acc[mf][nf][2], b2 = acc[mf][nf][3];
                float x1 = a1 * sc1.y - b1 * sc1.x;
                float y1 = b1 * sc1.y + a1 * sc1.x;
                float x2 = a2 * sc2.y - b2 * sc2.x;
                float y2 = b2 * sc2.y + a2 * sc2.x;
                __nv_bfloat16 hx1 = __float2bfloat16(x1), hy1 = __float2bfloat16(y1);
                __nv_bfloat16 hx2 = __float2bfloat16(x2), hy2 = __float2bfloat16(y2);
                *(__nv_bfloat162*)&g_Khi[(size_t)row1 * HD + col] = __halves2bfloat162(hx1, hy1);
                *(__nv_bfloat162*)&g_Khi[(size_t)row2 * HD + col] = __halves2bfloat162(hx2, hy2);
                *(__nv_bfloat162*)&g_Klo[(size_t)row1 * HD + col] = __halves2bfloat162(
                    __float2bfloat16(x1 - __bfloat162float(hx1)),
                    __float2bfloat16(y1 - __bfloat162float(hy1)));
                *(__nv_bfloat162*)&g_Klo[(size_t)row2 * HD + col] = __halves2bfloat162(
                    __float2bfloat16(x2 - __bfloat162float(hx2)),
                    __float2bfloat16(y2 - __bfloat162float(hy2)));
            }
    } else {
#pragma unroll
        for (int mf = 0; mf < 4; ++mf)
#pragma unroll
            for (int nf = 0; nf < 4; ++nf) {
                int row1 = r0 + mf * 16, row2 = row1 + 8;
                int col = (n0 - 2304) + lc0 + nf * 8;
                *(__half2*)&g_Vh[(size_t)row1 * HD + col] =
                    __floats2half2_rn(acc[mf][nf][0], acc[mf][nf][1]);
                *(__half2*)&g_Vh[(size_t)row2 * HD + col] =
                    __floats2half2_rn(acc[mf][nf][2], acc[mf][nf][3]);
            }
    }
}

// ===========================================================================
// HMMA causal flash attention — BN=64 key tiles.
// K(hi/lo): 2-stage ring.  V: single buffer, loaded at tile top, consumed
// in PV after mid-tile wait (~2000cyc of QK+softmax hides the load).
// Warp tile: S = m16 x n32 (sa[4][4]); PV m16 x n128.
// ===========================================================================
#define BN 64
#define KST 528
#define PST 144
#define KSTAGE 67584                       // Khi+Klo per stage (64 rows)
#define ST_KHI(s) ((s)*KSTAGE)
#define ST_KLO(s) (ST_KHI(s)+33792)
#define SVH    (2*KSTAGE)                  // 135168 (64x528)
#define SQLO   (SVH + 33792)               // 168960 (64x528)
#define SPHI   (SQLO + 33792)              // 202752 (64x144)
#define SRED   (SPHI + 64*PST)             // 211968
#define FLASH_SMEM (SRED + 1024)           // 212992

__device__ __forceinline__ void flash_load_k(uint32_t smb, int s, int s0, int tid,
                                             const __nv_bfloat16* kh,
                                             const __nv_bfloat16* kl) {
#pragma unroll
    for (int i2 = 0; i2 < 8; ++i2) {
        int c = tid + i2 * 256;
        int row = c >> 5, seg = c & 31;
        size_t go = (size_t)(s0 + row) * 512 + seg * 16;
        uint32_t so = row * KST + seg * 16;
        cpa16(smb + ST_KHI(s) + so, (const char*)kh + go);
        cpa16(smb + ST_KLO(s) + so, (const char*)kl + go);
    }
    CP_COMMIT();
}

__device__ __forceinline__ void flash_load_v(uint32_t smb, int s0, int tid,
                                             const __half* vh) {
#pragma unroll
    for (int i2 = 0; i2 < 8; ++i2) {
        int c = tid + i2 * 256;
        int row = c >> 5, seg = c & 31;
        cpa16(smb + SVH + row * KST + seg * 16,
              (const char*)vh + (size_t)(s0 + row) * 512 + seg * 16);
    }
    CP_COMMIT();
}

__global__ __launch_bounds__(256) void flash_hmma() {
    extern __shared__ __align__(128) char sm[];
    uint32_t smb = s2u(sm);
    const int tid = threadIdx.x, lane = tid & 31, wid = tid >> 5;
    const int wm = wid >> 1, wn = wid & 1;
    const int bx = gridDim.x - 1 - blockIdx.x;   // heavy tiles first
    const int n = blockIdx.y, b = blockIdx.z;
    const int q0 = bx * 64;
    const size_t tb = (size_t)b * TT;

    const char* qh_g = (const char*)(g_Qsp + (size_t)(tb + q0) * DD + n * 256);
    const char* ql_g = (const char*)(g_Qsp + (size_t)TOK * DD
                                     + (size_t)(tb + q0) * DD + n * 256);
    const __nv_bfloat16* kh_g = g_Khi + tb * 256;
    const __nv_bfloat16* kl_g = g_Klo + tb * 256;
    const __half* vh_g = g_Vh + tb * 256;

    // ---- stage Q: hi -> stage-1 Khi slot (transient), lo -> SQLO
#pragma unroll
    for (int i2 = 0; i2 < 8; ++i2) {
        int c = tid + i2 * 256;
        int row = c >> 5, seg = c & 31;
        cpa16(smb + ST_KHI(1) + row * KST + seg * 16, qh_g + (size_t)row * 4096 + seg * 16);
        cpa16(smb + SQLO + row * KST + seg * 16,      ql_g + (size_t)row * 4096 + seg * 16);
    }
    CP_COMMIT();
    CP_WAIT(0);
    __syncthreads();

    const uint32_t a_base = (uint32_t)((wm * 16 + (lane & 15)) * KST + (lane >> 4) * 16);
    uint32_t qh[16][4];
#pragma unroll
    for (int ks = 0; ks < 16; ++ks)
        LDSM4(qh[ks][0], qh[ks][1], qh[ks][2], qh[ks][3],
              smb + ST_KHI(1) + a_base + ks * 32);
    // issue K(0) into stage 0 (no clash with Qhi in stage 1)
    flash_load_k(smb, 0, 0, tid, kh_g, kl_g);

    float o[16][4];
#pragma unroll
    for (int nf = 0; nf < 16; ++nf)
#pragma unroll
        for (int r = 0; r < 4; ++r) o[nf][r] = 0.f;
    float m1 = -1e30f, m2 = -1e30f, l1 = 0.f, l2 = 0.f;

    const int grow1 = wm * 16 + (lane >> 2);
    const int grow2 = grow1 + 8;
    const int ccol = 2 * (lane & 3);
    float* rmaxs = (float*)(sm + SRED);
    float* rsums = (float*)(sm + SRED + 512);
    const uint32_t b_base = (uint32_t)((wn * 32 + ((lane >> 4) << 3) + (lane & 7)) * KST
                                       + ((lane >> 3) & 1) * 16);
    const uint32_t p_base = (uint32_t)((wm * 16 + (lane & 15)) * PST + (lane >> 4) * 16);
    const uint32_t v_base = (uint32_t)((lane & 15) * KST + wn * 256 + (lane >> 4) * 16);

    const int ntiles = bx + 1;
    for (int kt = 0; kt < ntiles; ++kt) {
        const int s = kt & 1;
        const bool haveK = (kt + 1 < ntiles);
        __syncthreads();                 // PV(kt-1) done -> Vs reusable; qh loaded (kt=0)
        flash_load_v(smb, kt * BN, tid, vh_g);
        if (haveK) {
            flash_load_k(smb, s ^ 1, (kt + 1) * BN, tid, kh_g, kl_g);
            CP_WAIT(2);                  // K(kt) drained; V(kt), K(kt+1) in flight
        } else {
            CP_WAIT(1);                  // K(kt) drained; V(kt) in flight
        }
        __syncthreads();                 // K(kt) visible to all warps

        // ---- S = Q K^T (3x split), warp tile m16 x n32
        float sa[4][4];
#pragma unroll
        for (int nf = 0; nf < 4; ++nf)
#pragma unroll
            for (int r = 0; r < 4; ++r) sa[nf][r] = 0.f;
#pragma unroll
        for (int ks = 0; ks < 16; ++ks) {
            uint32_t ql[4];
            LDSM4(ql[0], ql[1], ql[2], ql[3], smb + SQLO + a_base + ks * 32);
            uint32_t bh[8], bl[8];
#pragma unroll
            for (int pr = 0; pr < 2; ++pr) {
                uint32_t ba = smb + ST_KHI(s) + b_base + pr * (16 * KST) + ks * 32;
                LDSM4(bh[4 * pr + 0], bh[4 * pr + 1], bh[4 * pr + 2], bh[4 * pr + 3], ba);
                LDSM4(bl[4 * pr + 0], bl[4 * pr + 1], bl[4 * pr + 2], bl[4 * pr + 3],
                      ba + 33792);
            }
#pragma unroll
            for (int nf = 0; nf < 4; ++nf) {
                MMA16816(sa[nf], qh[ks], bh[2 * nf], bh[2 * nf + 1]);
                MMA16816(sa[nf], qh[ks], bl[2 * nf], bl[2 * nf + 1]);
                MMA16816(sa[nf], ql,     bh[2 * nf], bh[2 * nf + 1]);
            }
        }

        // ---- causal mask (only last tile)
        const int s0 = kt * BN;
        if (kt == bx) {
            const int qr1 = q0 + grow1, qr2 = q0 + grow2;
#pragma unroll
            for (int nf = 0; nf < 4; ++nf) {
                int c0 = s0 + wn * 32 + nf * 8 + ccol;
                if (c0     > qr1) sa[nf][0] = -1e30f;
                if (c0 + 1 > qr1) sa[nf][1] = -1e30f;
                if (c0     > qr2) sa[nf][2] = -1e30f;
                if (c0 + 1 > qr2) sa[nf][3] = -1e30f;
            }
        }

        // ---- online softmax (once per 64 keys)
        float pm1 = -1e30f, pm2 = -1e30f;
#pragma unroll
        for (int nf = 0; nf < 4; ++nf) {
            pm1 = fmaxf(pm1, fmaxf(sa[nf][0], sa[nf][1]));
            pm2 = fmaxf(pm2, fmaxf(sa[nf][2], sa[nf][3]));
        }
        pm1 = fmaxf(pm1, __shfl_xor_sync(0xffffffffu, pm1, 1));
        pm1 = fmaxf(pm1, __shfl_xor_sync(0xffffffffu, pm1, 2));
        pm2 = fmaxf(pm2, __shfl_xor_sync(0xffffffffu, pm2, 1));
        pm2 = fmaxf(pm2, __shfl_xor_sync(0xffffffffu, pm2, 2));
        if ((lane & 3) == 0) {
            rmaxs[wn * 64 + grow1] = pm1;
            rmaxs[wn * 64 + grow2] = pm2;
        }
        __syncthreads();
        float mn1 = fmaxf(m1, fmaxf(rmaxs[grow1], rmaxs[64 + grow1]));
        float mn2 = fmaxf(m2, fmaxf(rmaxs[grow2], rmaxs[64 + grow2]));
        float al1 = __expf(m1 - mn1), al2 = __expf(m2 - mn2);
        m1 = mn1; m2 = mn2;

        float ps1 = 0.f, ps2 = 0.f;
#pragma unroll
        for (int nf = 0; nf < 4; ++nf) {
            float e0 = __expf(sa[nf][0] - mn1), e1 = __expf(sa[nf][1] - mn1);
            float e2 = __expf(sa[nf][2] - mn2), e3 = __expf(sa[nf][3] - mn2);
            ps1 += e0 + e1; ps2 += e2 + e3;
            int colB = (wn * 32 + nf * 8 + ccol) * 2;
            *(__half2*)(sm + SPHI + grow1 * PST + colB) = __floats2half2_rn(e0, e1);
            *(__half2*)(sm + SPHI + grow2 * PST + colB) = __floats2half2_rn(e2, e3);
        }
        ps1 += __shfl_xor_sync(0xffffffffu, ps1, 1);
        ps1 += __shfl_xor_sync(0xffffffffu, ps1, 2);
        ps2 += __shfl_xor_sync(0xffffffffu, ps2, 1);
        ps2 += __shfl_xor_sync(0xffffffffu, ps2, 2);
        if ((lane & 3) == 0) {
            rsums[wn * 64 + grow1] = ps1;
            rsums[wn * 64 + grow2] = ps2;
        }
#pragma unroll
        for (int nf = 0; nf < 16; ++nf) {
            o[nf][0] *= al1; o[nf][1] *= al1;
            o[nf][2] *= al2; o[nf][3] *= al2;
        }
        if (haveK) { CP_WAIT(1); } else { CP_WAIT(0); }   // V(kt) landed
        __syncthreads();                                  // P + V visible
        l1 = l1 * al1 + rsums[grow1] + rsums[64 + grow1];
        l2 = l2 * al2 + rsums[grow2] + rsums[64 + grow2];

        // ---- O += P V  (fp16 P, 4 k-steps over 64 keys)
#pragma unroll
        for (int ks = 0; ks < 4; ++ks) {
            uint32_t ph[4];
            LDSM4(ph[0], ph[1], ph[2], ph[3], smb + SPHI + p_base + ks * 32);
#pragma unroll
            for (int nb = 0; nb < 8; ++nb) {
                uint32_t v0, v1, v2, v3;
                LDSM4T(v0, v1, v2, v3,
                       smb + SVH + v_base + ks * (16 * KST) + nb * 32);
                MMAF16(o[2 * nb],     ph, v0, v1);
                MMAF16(o[2 * nb + 1], ph, v2, v3);
            }
        }
    }

    // ---- epilogue: normalize, bf16 split into out-GEMM A buffers
    float i1 = 1.f / l1, i2 = 1.f / l2;
#pragma unroll
    for (int nf = 0; nf < 16; ++nf) {
        int col = n * 256 + wn * 128 + nf * 8 + ccol;
        size_t o1 = (tb + q0 + grow1) * (size_t)DD + col;
        size_t o2 = (tb + q0 + grow2) * (size_t)DD + col;
        float v0 = o[nf][0] * i1, v1 = o[nf][1] * i1;
        float v2 = o[nf][2] * i2, v3 = o[nf][3] * i2;
        __nv_bfloat16 h0 = __float2bfloat16(v0), h1 = __float2bfloat16(v1);
        __nv_bfloat16 h2 = __float2bfloat16(v2), h3 = __float2bfloat16(v3);
        *(__nv_bfloat162*)&g_Ahi[o1] = __halves2bfloat162(h0, h1);
        *(__nv_bfloat162*)&g_Ahi[o2] = __halves2bfloat162(h2, h3);
        *(__nv_bfloat162*)&g_Alo[o1] = __halves2bfloat162(
            __float2bfloat16(v0 - __bfloat162float(h0)),
            __float2bfloat16(v1 - __bfloat162float(h1)));
        *(__nv_bfloat162*)&g_Alo[o2] = __halves2bfloat162(
            __float2bfloat16(v2 - __bfloat162float(h2)),
            __float2bfloat16(v3 - __bfloat162float(h3)));
    }
}

// ===========================================================================
// launch — inputs: 0=x, 1=segment_pos, 2=attn_mask, 3=q_w, 4=kv_w, 5=out_w
// ===========================================================================
extern "C" void kernel_launch(void* const* d_in, const int* in_sizes, int n_in,
                              void* d_out, int out_size) {
    (void)in_sizes; (void)n_in; (void)out_size;
    const float* x   = (const float*)d_in[0];
    const float* qw  = (const float*)d_in[3];
    const float* kvw = (const float*)d_in[4];
    const float* ow  = (const float*)d_in[5];
    float* out = (float*)d_out;

    cudaFuncSetAttribute(gemm3x_kernel,
                         cudaFuncAttributeMaxDynamicSharedMemorySize, GSM_TOTAL);
    cudaFuncSetAttribute(flash_hmma,
                         cudaFuncAttributeMaxDynamicSharedMemorySize, FLASH_SMEM);

    rope_table<<<128, 256>>>();
    transpose_qkvw<<<dim3(HD / 32, DD / 32, 10), dim3(32, 8)>>>(qw, kvw);
    convert_split<<<(TOK * DD) / 4 / 256, 256>>>(x);

    // QKV projection + fused rope/scale/split epilogue
    gemm3x_kernel<<<dim3(NQKV / 128, TOK / 128), 256, GSM_TOTAL>>>(nullptr, 0);

    transpose_outw<<<dim3(DD / 32, DD / 32), dim3(32, 8)>>>(ow);

    // HMMA flash attention (writes enc bf16-split into g_Ahi/g_Alo)
    flash_hmma<<<dim3(TT / 64, NHEAD, BB), 256, FLASH_SMEM>>>();

    // Out projection
    gemm3x_kernel<<<dim3(DD / 128, TOK / 128), 256, GSM_TOTAL>>>(out, 1);
}

// round 16
// speedup vs baseline: 1.3872x; 1.1482x over previous
#include <cuda_runtime.h>
#include <cuda_bf16.h>
#include <cuda_fp16.h>
#include <math.h>
#include <stdint.h>

// Problem constants
#define BB 2
#define TT 4096
#define DD 2048
#define NHEAD 8
#define HD 256
#define TOK (BB*TT)           // 8192
#define NQKV 2560             // 8*256 Q + 256 K + 256 V

// ---------------- scratch (device globals; no allocation allowed) ----------
__device__ __nv_bfloat16 g_Qsp[(size_t)2 * TOK * DD];   // Q fp16 single (reinterp)
__device__ __nv_bfloat16 g_Ahi[(size_t)TOK * DD];       // x-split hi; later enc fp16
__device__ __nv_bfloat16 g_Alo[(size_t)TOK * DD];       // x-split lo
__device__ __nv_bfloat16 g_Bhi[(size_t)NQKV * DD];      // weights hi (bf16 qkv / fp16 out)
__device__ __nv_bfloat16 g_Blo[(size_t)NQKV * DD];      // weights lo
__device__ __nv_bfloat16 g_Khi[(size_t)TOK * HD];       // K fp16 hi (reinterp)
__device__ __nv_bfloat16 g_Klo[(size_t)TOK * HD];       // K fp16 lo (reinterp)
__device__ __half        g_Vh [(size_t)TOK * HD];
__device__ float2        g_ropetab[(size_t)TT * 128];

// =================== ptx helpers ========================
__device__ __forceinline__ uint32_t s2u(const void* p) {
    uint32_t a;
    asm("{ .reg .u64 t; cvta.to.shared.u64 t, %1; cvt.u32.u64 %0, t; }"
        : "=r"(a) : "l"(p));
    return a;
}
__device__ __forceinline__ void cpa16(uint32_t s, const void* g) {
    asm volatile("cp.async.cg.shared.global [%0], [%1], 16;" :: "r"(s), "l"(g));
}
#define CP_COMMIT()  asm volatile("cp.async.commit_group;" ::: "memory")
#define CP_WAIT(N)   asm volatile("cp.async.wait_group %0;" :: "n"(N) : "memory")

#define LDSM4(r0, r1, r2, r3, addr) \
    asm volatile("ldmatrix.sync.aligned.m8n8.x4.shared.b16 {%0,%1,%2,%3}, [%4];" \
                 : "=r"(r0), "=r"(r1), "=r"(r2), "=r"(r3) : "r"(addr))

#define LDSM4T(r0, r1, r2, r3, addr) \
    asm volatile("ldmatrix.sync.aligned.m8n8.x4.trans.shared.b16 {%0,%1,%2,%3}, [%4];" \
                 : "=r"(r0), "=r"(r1), "=r"(r2), "=r"(r3) : "r"(addr))

#define MMA16816(d, a, b0, b1) \
    asm volatile("mma.sync.aligned.m16n8k16.row.col.f32.bf16.bf16.f32 " \
                 "{%0,%1,%2,%3}, {%4,%5,%6,%7}, {%8,%9}, {%0,%1,%2,%3};" \
                 : "+f"((d)[0]), "+f"((d)[1]), "+f"((d)[2]), "+f"((d)[3]) \
                 : "r"((a)[0]), "r"((a)[1]), "r"((a)[2]), "r"((a)[3]), \
                   "r"(b0), "r"(b1))

#define MMAF16(d, a, b0, b1) \
    asm volatile("mma.sync.aligned.m16n8k16.row.col.f32.f16.f16.f32 " \
                 "{%0,%1,%2,%3}, {%4,%5,%6,%7}, {%8,%9}, {%0,%1,%2,%3};" \
                 : "+f"((d)[0]), "+f"((d)[1]), "+f"((d)[2]), "+f"((d)[3]) \
                 : "r"((a)[0]), "r"((a)[1]), "r"((a)[2]), "r"((a)[3]), \
                   "r"(b0), "r"(b1))

// ===========================================================================
// RoPE table
// ===========================================================================
__global__ void rope_table() {
    __shared__ double u1s;
    const int i = blockIdx.x;
    if (threadIdx.x == 0)
        u1s = pow(10000.0, -(double)i / 128.0) * 0.15915494309189533576;
    __syncthreads();
    const double u1 = u1s;
    for (int t = threadIdx.x; t < TT; t += blockDim.x) {
        double u = (double)t * u1;
        float x2 = (float)(2.0 * (u - trunc(u)));
        float s, c;
        sincospif(x2, &s, &c);
        g_ropetab[t * 128 + i] = make_float2(s, c);
    }
}

// ===========================================================================
// Weight prep
// ===========================================================================
__global__ void transpose_qkvw(const float* __restrict__ qw,
                               const float* __restrict__ kvw) {
    __shared__ float t[32][33];
    const int g = blockIdx.z;
    const float* slab = (g < 8) ? qw + (size_t)g * DD * HD
                                : kvw + (size_t)(g - 8) * DD * HD;
    const int h0 = blockIdx.x * 32, k0 = blockIdx.y * 32;
    const int c = threadIdx.x, r0 = threadIdx.y;
#pragma unroll
    for (int i = 0; i < 32; i += 8)
        t[r0 + i][c] = slab[(size_t)(k0 + r0 + i) * HD + h0 + c];
    __syncthreads();
#pragma unroll
    for (int i = 0; i < 32; i += 8) {
        float v = t[c][r0 + i];
        int h = h0 + r0 + i;
        int hp = (g == 9) ? h : ((h < 128) ? 2 * h : 2 * (h - 128) + 1);
        size_t o = (size_t)(g * 256 + hp) * DD + k0 + c;
        __nv_bfloat16 hi = __float2bfloat16(v);
        g_Bhi[o] = hi;
        g_Blo[o] = __float2bfloat16(v - __bfloat162float(hi));
    }
}

// out_w -> fp16 hi/lo, K-major [d][nh] (reinterpreted storage)
__global__ void transpose_outw(const float* __restrict__ ow) {
    __shared__ float t[32][33];
    const int j0 = blockIdx.x * 32, k0 = blockIdx.y * 32;
    const int c = threadIdx.x, r0 = threadIdx.y;
    __half* bh = (__half*)g_Bhi;
    __half* bl = (__half*)g_Blo;
#pragma unroll
    for (int i = 0; i < 32; i += 8)
        t[r0 + i][c] = ow[(size_t)(k0 + r0 + i) * DD + j0 + c];
    __syncthreads();
#pragma unroll
    for (int i = 0; i < 32; i += 8) {
        float v = t[c][r0 + i];
        size_t o = (size_t)(j0 + r0 + i) * DD + k0 + c;
        __half hi = __float2half_rn(v);
        bh[o] = hi;
        bl[o] = __float2half_rn(v - __half2float(hi));
    }
}

__global__ void convert_split(const float* __restrict__ src) {
    size_t i = (size_t)blockIdx.x * blockDim.x + threadIdx.x;
    float4 v = ((const float4*)src)[i];
    __nv_bfloat16 hx = __float2bfloat16(v.x), hy = __float2bfloat16(v.y);
    __nv_bfloat16 hz = __float2bfloat16(v.z), hw = __float2bfloat16(v.w);
    __nv_bfloat162* h2 = (__nv_bfloat162*)g_Ahi;
    __nv_bfloat162* l2 = (__nv_bfloat162*)g_Alo;
    h2[2 * i]     = __halves2bfloat162(hx, hy);
    h2[2 * i + 1] = __halves2bfloat162(hz, hw);
    l2[2 * i]     = __halves2bfloat162(
        __float2bfloat16(v.x - __bfloat162float(hx)),
        __float2bfloat16(v.y - __bfloat162float(hy)));
    l2[2 * i + 1] = __halves2bfloat162(
        __float2bfloat16(v.z - __bfloat162float(hz)),
        __float2bfloat16(v.w - __bfloat162float(hw)));
}

// ===========================================================================
// QKV GEMM — 3xBF16, 2-stage ring, 2 CTAs/SM.  Fused epilogue:
// Q -> single fp16 (rope+scale), K -> fp16 hi/lo (rope), V -> fp16.
// ===========================================================================
#define KC 32
#define TROW 80
#define TILEB (128 * TROW)
#define STAGEB (4 * TILEB)
#define GSM_TOTAL (2 * STAGEB)

__device__ __forceinline__ void load_stage(uint32_t smb, int s, int k0, int tid,
                                           const __nv_bfloat16* const* base) {
    uint32_t sb = smb + s * STAGEB;
#pragma unroll
    for (int j = 0; j < 8; ++j) {
        int c = tid + j * 256;
        const int tile = j >> 1;
        int inner = c & 511;
        int row = inner >> 2, seg = inner & 3;
        const __nv_bfloat16* gp = base[tile] + (size_t)row * DD + k0 + seg * 8;
        cpa16(sb + tile * TILEB + row * TROW + seg * 16, gp);
    }
    CP_COMMIT();
}

__global__ __launch_bounds__(256, 2) void gemm_qkv_kernel() {
    extern __shared__ __align__(128) char sm[];
    uint32_t smb = s2u(sm);
    const int tid = threadIdx.x;
    const int lane = tid & 31, wid = tid >> 5;
    const int wm = wid & 1, wn = wid >> 1;
    const int n0 = blockIdx.x * 128;
    const int m0 = blockIdx.y * 128;

    const __nv_bfloat16* base[4] = {
        g_Ahi + (size_t)m0 * DD, g_Alo + (size_t)m0 * DD,
        g_Bhi + (size_t)n0 * DD, g_Blo + (size_t)n0 * DD };

    float acc[4][4][4];
#pragma unroll
    for (int i = 0; i < 4; ++i)
#pragma unroll
        for (int j = 0; j < 4; ++j)
#pragma unroll
            for (int r = 0; r < 4; ++r) acc[i][j][r] = 0.f;

    const uint32_t a_off = (uint32_t)((wm * 64 + (lane & 15)) * TROW
                                      + (lane >> 4) * 16);
    const uint32_t b_off = (uint32_t)((wn * 32 + (lane >> 4) * 8 + (lane & 7)) * TROW
                                      + ((lane >> 3) & 1) * 16);

    load_stage(smb, 0, 0, tid, base);

    const int NIT = DD / KC;
    for (int it = 0; it < NIT; ++it) {
        const int s = it & 1;
        if (it + 1 < NIT) {
            load_stage(smb, s ^ 1, (it + 1) * KC, tid, base);
            CP_WAIT(1);
        } else {
            CP_WAIT(0);
        }
        __syncthreads();

        const uint32_t st = smb + s * STAGEB;
#pragma unroll
        for (int ks = 0; ks < 2; ++ks) {
            const uint32_t ko = ks * 32;
            uint32_t bhi[4][2], blo[4][2];
#pragma unroll
            for (int pr = 0; pr < 2; ++pr) {
                uint32_t ba = st + 2 * TILEB + b_off + pr * (16 * TROW) + ko;
                LDSM4(bhi[2 * pr][0], bhi[2 * pr][1],
                      bhi[2 * pr + 1][0], bhi[2 * pr + 1][1], ba);
                LDSM4(blo[2 * pr][0], blo[2 * pr][1],
                      blo[2 * pr + 1][0], blo[2 * pr + 1][1], ba + TILEB);
            }
#pragma unroll
            for (int mf = 0; mf < 4; ++mf) {
                uint32_t ahi[4], alo[4];
                uint32_t aa = st + a_off + mf * (16 * TROW) + ko;
                LDSM4(ahi[0], ahi[1], ahi[2], ahi[3], aa);
                LDSM4(alo[0], alo[1], alo[2], alo[3], aa + TILEB);
#pragma unroll
                for (int nf = 0; nf < 4; ++nf) {
                    MMA16816(acc[mf][nf], ahi, bhi[nf][0], bhi[nf][1]);
                    MMA16816(acc[mf][nf], ahi, blo[nf][0], blo[nf][1]);
                    MMA16816(acc[mf][nf], alo, bhi[nf][0], bhi[nf][1]);
                }
            }
        }
        __syncthreads();
    }

    const int r0 = m0 + wm * 64 + (lane >> 2);
    const int lc0 = wn * 32 + 2 * (lane & 3);

    if (n0 < 2048) {
        // Q: rope + 1/16 scale -> single fp16 (cols interleaved)
        __half* Qh = (__half*)g_Qsp;
#pragma unroll
        for (int mf = 0; mf < 4; ++mf)
#pragma unroll
            for (int nf = 0; nf < 4; ++nf) {
                int row1 = r0 + mf * 16, row2 = row1 + 8;
                int col = n0 + lc0 + nf * 8;
                int ri = (col & 255) >> 1;
                float2 sc1 = g_ropetab[(row1 & (TT - 1)) * 128 + ri];
                float2 sc2 = g_ropetab[(row2 & (TT - 1)) * 128 + ri];
                float a1 = acc[mf][nf][0], b1 = acc[mf][nf][1];
                float a2 = acc[mf][nf][2], b2 = acc[mf][nf][3];
                float x1 = (a1 * sc1.y - b1 * sc1.x) * 0.0625f;
                float y1 = (b1 * sc1.y + a1 * sc1.x) * 0.0625f;
                float x2 = (a2 * sc2.y - b2 * sc2.x) * 0.0625f;
                float y2 = (b2 * sc2.y + a2 * sc2.x) * 0.0625f;
                *(__half2*)&Qh[(size_t)row1 * DD + col] = __floats2half2_rn(x1, y1);
                *(__half2*)&Qh[(size_t)row2 * DD + col] = __floats2half2_rn(x2, y2);
            }
    } else if (n0 < 2304) {
        // K: rope -> fp16 hi/lo (cols interleaved)
        __half* Kh = (__half*)g_Khi;
        __half* Kl = (__half*)g_Klo;
#pragma unroll
        for (int mf = 0; mf < 4; ++mf)
#pragma unroll
            for (int nf = 0; nf < 4; ++nf) {
                int row1 = r0 + mf * 16, row2 = row1 + 8;
                int col = (n0 - 2048) + lc0 + nf * 8;
                int ri = col >> 1;
                float2 sc1 = g_ropetab[(row1 & (TT - 1)) * 128 + ri];
                float2 sc2 = g_ropetab[(row2 & (TT - 1)) * 128 + ri];
                float a1 = acc[mf][nf][0], b1 = acc[mf][nf][1];
                float a2 = acc[mf][nf][2], b2 = acc[mf][nf][3];
                float x1 = a1 * sc1.y - b1 * sc1.x;
                float y1 = b1 * sc1.y + a1 * sc1.x;
                float x2 = a2 * sc2.y - b2 * sc2.x;
                float y2 = b2 * sc2.y + a2 * sc2.x;
                __half hx1 = __float2half_rn(x1), hy1 = __float2half_rn(y1);
                __half hx2 = __float2half_rn(x2), hy2 = __float2half_rn(y2);
                *(__half2*)&Kh[(size_t)row1 * HD + col] = __halves2half2(hx1, hy1);
                *(__half2*)&Kh[(size_t)row2 * HD + col] = __halves2half2(hx2, hy2);
                *(__half2*)&Kl[(size_t)row1 * HD + col] = __halves2half2(
                    __float2half_rn(x1 - __half2float(hx1)),
                    __float2half_rn(y1 - __half2float(hy1)));
                *(__half2*)&Kl[(size_t)row2 * HD + col] = __halves2half2(
                    __float2half_rn(x2 - __half2float(hx2)),
                    __float2half_rn(y2 - __half2float(hy2)));
            }
    } else {
#pragma unroll
        for (int mf = 0; mf < 4; ++mf)
#pragma unroll
            for (int nf = 0; nf < 4; ++nf) {
                int row1 = r0 + mf * 16, row2 = row1 + 8;
                int col = (n0 - 2304) + lc0 + nf * 8;
                *(__half2*)&g_Vh[(size_t)row1 * HD + col] =
                    __floats2half2_rn(acc[mf][nf][0], acc[mf][nf][1]);
                *(__half2*)&g_Vh[(size_t)row2 * HD + col] =
                    __floats2half2_rn(acc[mf][nf][2], acc[mf][nf][3]);
            }
    }
}

// ===========================================================================
// OUT GEMM — 2xFP16 (A = enc single fp16, B = fp16 hi+lo), 2-stage ring,
// 2 CTAs/SM.  out = fp32.
// ===========================================================================
#define TILE2B (128 * TROW)             // 10240
#define STAGE2B (3 * TILE2B)            // 30720
#define G2SM (2 * STAGE2B)              // 61440

__device__ __forceinline__ void load_stage2(uint32_t smb, int s, int k0, int tid,
                                            const __half* a,
                                            const __half* bh, const __half* bl) {
    uint32_t sb = smb + s * STAGE2B;
#pragma unroll
    for (int j = 0; j < 6; ++j) {
        int c = tid + j * 256;
        const int tile = j >> 1;
        int inner = c & 511;
        int row = inner >> 2, seg = inner & 3;
        const __half* gp = (tile == 0 ? a : tile == 1 ? bh : bl)
                           + (size_t)row * DD + k0 + seg * 8;
        cpa16(sb + tile * TILE2B + row * TROW + seg * 16, gp);
    }
    CP_COMMIT();
}

__global__ __launch_bounds__(256, 2) void gemm_out_kernel(float* outp) {
    extern __shared__ __align__(128) char sm[];
    uint32_t smb = s2u(sm);
    const int tid = threadIdx.x;
    const int lane = tid & 31, wid = tid >> 5;
    const int wm = wid & 1, wn = wid >> 1;
    const int n0 = blockIdx.x * 128;
    const int m0 = blockIdx.y * 128;

    const __half* aB = (const __half*)g_Ahi + (size_t)m0 * DD;
    const __half* bH = (const __half*)g_Bhi + (size_t)n0 * DD;
    const __half* bL = (const __half*)g_Blo + (size_t)n0 * DD;

    float acc[4][4][4];
#pragma unroll
    for (int i = 0; i < 4; ++i)
#pragma unroll
        for (int j = 0; j < 4; ++j)
#pragma unroll
            for (int r = 0; r < 4; ++r) acc[i][j][r] = 0.f;

    const uint32_t a_off = (uint32_t)((wm * 64 + (lane & 15)) * TROW
                                      + (lane >> 4) * 16);
    const uint32_t b_off = (uint32_t)((wn * 32 + (lane >> 4) * 8 + (lane & 7)) * TROW
                                      + ((lane >> 3) & 1) * 16);

    load_stage2(smb, 0, 0, tid, aB, bH, bL);

    const int NIT = DD / KC;
    for (int it = 0; it < NIT; ++it) {
        const int s = it & 1;
        if (it + 1 < NIT) {
            load_stage2(smb, s ^ 1, (it + 1) * KC, tid, aB, bH, bL);
            CP_WAIT(1);
        } else {
            CP_WAIT(0);
        }
        __syncthreads();

        const uint32_t st = smb + s * STAGE2B;
#pragma unroll
        for (int ks = 0; ks < 2; ++ks) {
            const uint32_t ko = ks * 32;
            uint32_t bhi[4][2], blo[4][2];
#pragma unroll
            for (int pr = 0; pr < 2; ++pr) {
                uint32_t ba = st + TILE2B + b_off + pr * (16 * TROW) + ko;
                LDSM4(bhi[2 * pr][0], bhi[2 * pr][1],
                      bhi[2 * pr + 1][0], bhi[2 * pr + 1][1], ba);
                LDSM4(blo[2 * pr][0], blo[2 * pr][1],
                      blo[2 * pr + 1][0], blo[2 * pr + 1][1], ba + TILE2B);
            }
#pragma unroll
            for (int mf = 0; mf < 4; ++mf) {
                uint32_t af[4];
                LDSM4(af[0], af[1], af[2], af[3],
                      st + a_off + mf * (16 * TROW) + ko);
#pragma unroll
                for (int nf = 0; nf < 4; ++nf) {
                    MMAF16(acc[mf][nf], af, bhi[nf][0], bhi[nf][1]);
                    MMAF16(acc[mf][nf], af, blo[nf][0], blo[nf][1]);
                }
            }
        }
        __syncthreads();
    }

    const int r0 = m0 + wm * 64 + (lane >> 2);
    const int c0 = n0 + wn * 32 + 2 * (lane & 3);
#pragma unroll
    for (int mf = 0; mf < 4; ++mf)
#pragma unroll
        for (int nf = 0; nf < 4; ++nf) {
            float* p0 = outp + (size_t)(r0 + mf * 16) * DD + c0 + nf * 8;
            *(float2*)p0 = make_float2(acc[mf][nf][0], acc[mf][nf][1]);
            float* p1 = p0 + 8 * DD;
            *(float2*)p1 = make_float2(acc[mf][nf][2], acc[mf][nf][3]);
        }
}

// ===========================================================================
// Flash attention — BN=64, QK = 2xFP16 (Q single, K hi+lo), PV fp16.
// K 2-stage ring; V single-buffered; enc epilogue -> single fp16.
// ===========================================================================
#define BN 64
#define KST 528
#define PST 144
#define KSTAGE 67584
#define ST_KHI(s) ((s)*KSTAGE)
#define ST_KLO(s) (ST_KHI(s)+33792)
#define SVH    (2*KSTAGE)                  // 135168
#define SPHI   (SVH + 33792)               // 168960
#define SRED   (SPHI + 64*PST)             // 178176
#define FLASH_SMEM (SRED + 1024)           // 179200

__device__ __forceinline__ void flash_load_k(uint32_t smb, int s, int s0, int tid,
                                             const __half* kh, const __half* kl) {
#pragma unroll
    for (int i2 = 0; i2 < 8; ++i2) {
        int c = tid + i2 * 256;
        int row = c >> 5, seg = c & 31;
        size_t go = (size_t)(s0 + row) * 512 + seg * 16;
        uint32_t so = row * KST + seg * 16;
        cpa16(smb + ST_KHI(s) + so, (const char*)kh + go);
        cpa16(smb + ST_KLO(s) + so, (const char*)kl + go);
    }
    CP_COMMIT();
}

__device__ __forceinline__ void flash_load_v(uint32_t smb, int s0, int tid,
                                             const __half* vh) {
#pragma unroll
    for (int i2 = 0; i2 < 8; ++i2) {
        int c = tid + i2 * 256;
        int row = c >> 5, seg = c & 31;
        cpa16(smb + SVH + row * KST + seg * 16,
              (const char*)vh + (size_t)(s0 + row) * 512 + seg * 16);
    }
    CP_COMMIT();
}

__global__ __launch_bounds__(256) void flash_hmma() {
    extern __shared__ __align__(128) char sm[];
    uint32_t smb = s2u(sm);
    const int tid = threadIdx.x, lane = tid & 31, wid = tid >> 5;
    const int wm = wid >> 1, wn = wid & 1;
    const int bx = gridDim.x - 1 - blockIdx.x;
    const int n = blockIdx.y, b = blockIdx.z;
    const int q0 = bx * 64;
    const size_t tb = (size_t)b * TT;

    const char* qh_g = (const char*)((const __half*)g_Qsp
                                     + (size_t)(tb + q0) * DD + n * 256);
    const __half* kh_g = (const __half*)g_Khi + tb * 256;
    const __half* kl_g = (const __half*)g_Klo + tb * 256;
    const __half* vh_g = g_Vh + tb * 256;

    // ---- stage Q (single fp16) through stage-1 Khi slot
#pragma unroll
    for (int i2 = 0; i2 < 8; ++i2) {
        int c = tid + i2 * 256;
        int row = c >> 5, seg = c & 31;
        cpa16(smb + ST_KHI(1) + row * KST + seg * 16,
              qh_g + (size_t)row * 4096 + seg * 16);
    }
    CP_COMMIT();
    CP_WAIT(0);
    __syncthreads();

    const uint32_t a_base = (uint32_t)((wm * 16 + (lane & 15)) * KST + (lane >> 4) * 16);
    uint32_t qh[16][4];
#pragma unroll
    for (int ks = 0; ks < 16; ++ks)
        LDSM4(qh[ks][0], qh[ks][1], qh[ks][2], qh[ks][3],
              smb + ST_KHI(1) + a_base + ks * 32);
    flash_load_k(smb, 0, 0, tid, kh_g, kl_g);

    float o[16][4];
#pragma unroll
    for (int nf = 0; nf < 16; ++nf)
#pragma unroll
        for (int r = 0; r < 4; ++r) o[nf][r] = 0.f;
    float m1 = -1e30f, m2 = -1e30f, l1 = 0.f, l2 = 0.f;

    const int grow1 = wm * 16 + (lane >> 2);
    const int grow2 = grow1 + 8;
    const int ccol = 2 * (lane & 3);
    float* rmaxs = (float*)(sm + SRED);
    float* rsums = (float*)(sm + SRED + 512);
    const uint32_t b_base = (uint32_t)((wn * 32 + ((lane >> 4) << 3) + (lane & 7)) * KST
                                       + ((lane >> 3) & 1) * 16);
    const uint32_t p_base = (uint32_t)((wm * 16 + (lane & 15)) * PST + (lane >> 4) * 16);
    const uint32_t v_base = (uint32_t)((lane & 15) * KST + wn * 256 + (lane >> 4) * 16);

    const int ntiles = bx + 1;
    for (int kt = 0; kt < ntiles; ++kt) {
        const int s = kt & 1;
        const bool haveK = (kt + 1 < ntiles);
        __syncthreads();
        flash_load_v(smb, kt * BN, tid, vh_g);
        if (haveK) {
            flash_load_k(smb, s ^ 1, (kt + 1) * BN, tid, kh_g, kl_g);
            CP_WAIT(2);
        } else {
            CP_WAIT(1);
        }
        __syncthreads();

        // ---- S = Q K^T (fp16: Q single x K hi+lo)
        float sa[4][4];
#pragma unroll
        for (int nf = 0; nf < 4; ++nf)
#pragma unroll
            for (int r = 0; r < 4; ++r) sa[nf][r] = 0.f;
#pragma unroll
        for (int ks = 0; ks < 16; ++ks) {
            uint32_t bh[8], bl[8];
#pragma unroll
            for (int pr = 0; pr < 2; ++pr) {
                uint32_t ba = smb + ST_KHI(s) + b_base + pr * (16 * KST) + ks * 32;
                LDSM4(bh[4 * pr + 0], bh[4 * pr + 1], bh[4 * pr + 2], bh[4 * pr + 3], ba);
                LDSM4(bl[4 * pr + 0], bl[4 * pr + 1], bl[4 * pr + 2], bl[4 * pr + 3],
                      ba + 33792);
            }
#pragma unroll
            for (int nf = 0; nf < 4; ++nf) {
                MMAF16(sa[nf], qh[ks], bh[2 * nf], bh[2 * nf + 1]);
                MMAF16(sa[nf], qh[ks], bl[2 * nf], bl[2 * nf + 1]);
            }
        }

        // ---- causal mask (last tile only)
        const int s0 = kt * BN;
        if (kt == bx) {
            const int qr1 = q0 + grow1, qr2 = q0 + grow2;
#pragma unroll
            for (int nf = 0; nf < 4; ++nf) {
                int c0 = s0 + wn * 32 + nf * 8 + ccol;
                if (c0     > qr1) sa[nf][0] = -1e30f;
                if (c0 + 1 > qr1) sa[nf][1] = -1e30f;
                if (c0     > qr2) sa[nf][2] = -1e30f;
                if (c0 + 1 > qr2) sa[nf][3] = -1e30f;
            }
        }

        // ---- online softmax
        float pm1 = -1e30f, pm2 = -1e30f;
#pragma unroll
        for (int nf = 0; nf < 4; ++nf) {
            pm1 = fmaxf(pm1, fmaxf(sa[nf][0], sa[nf][1]));
            pm2 = fmaxf(pm2, fmaxf(sa[nf][2], sa[nf][3]));
        }
        pm1 = fmaxf(pm1, __shfl_xor_sync(0xffffffffu, pm1, 1));
        pm1 = fmaxf(pm1, __shfl_xor_sync(0xffffffffu, pm1, 2));
        pm2 = fmaxf(pm2, __shfl_xor_sync(0xffffffffu, pm2, 1));
        pm2 = fmaxf(pm2, __shfl_xor_sync(0xffffffffu, pm2, 2));
        if ((lane & 3) == 0) {
            rmaxs[wn * 64 + grow1] = pm1;
            rmaxs[wn * 64 + grow2] = pm2;
        }
        __syncthreads();
        float mn1 = fmaxf(m1, fmaxf(rmaxs[grow1], rmaxs[64 + grow1]));
        float mn2 = fmaxf(m2, fmaxf(rmaxs[grow2], rmaxs[64 + grow2]));
        float al1 = __expf(m1 - mn1), al2 = __expf(m2 - mn2);
        m1 = mn1; m2 = mn2;

        float ps1 = 0.f, ps2 = 0.f;
#pragma unroll
        for (int nf = 0; nf < 4; ++nf) {
            float e0 = __expf(sa[nf][0] - mn1), e1 = __expf(sa[nf][1] - mn1);
            float e2 = __expf(sa[nf][2] - mn2), e3 = __expf(sa[nf][3] - mn2);
            ps1 += e0 + e1; ps2 += e2 + e3;
            int colB = (wn * 32 + nf * 8 + ccol) * 2;
            *(__half2*)(sm + SPHI + grow1 * PST + colB) = __floats2half2_rn(e0, e1);
            *(__half2*)(sm + SPHI + grow2 * PST + colB) = __floats2half2_rn(e2, e3);
        }
        ps1 += __shfl_xor_sync(0xffffffffu, ps1, 1);
        ps1 += __shfl_xor_sync(0xffffffffu, ps1, 2);
        ps2 += __shfl_xor_sync(0xffffffffu, ps2, 1);
        ps2 += __shfl_xor_sync(0xffffffffu, ps2, 2);
        if ((lane & 3) == 0) {
            rsums[wn * 64 + grow1] = ps1;
            rsums[wn * 64 + grow2] = ps2;
        }
#pragma unroll
        for (int nf = 0; nf < 16; ++nf) {
            o[nf][0] *= al1; o[nf][1] *= al1;
            o[nf][2] *= al2; o[nf][3] *= al2;
        }
        if (haveK) { CP_WAIT(1); } else { CP_WAIT(0); }
        __syncthreads();
        l1 = l1 * al1 + rsums[grow1] + rsums[64 + grow1];
        l2 = l2 * al2 + rsums[grow2] + rsums[64 + grow2];

        // ---- O += P V
#pragma unroll
        for (int ks = 0; ks < 4; ++ks) {
            uint32_t ph[4];
            LDSM4(ph[0], ph[1], ph[2], ph[3], smb + SPHI + p_base + ks * 32);
#pragma unroll
            for (int nb = 0; nb < 8; ++nb) {
                uint32_t v0, v1, v2, v3;
                LDSM4T(v0, v1, v2, v3,
                       smb + SVH + v_base + ks * (16 * KST) + nb * 32);
                MMAF16(o[2 * nb],     ph, v0, v1);
                MMAF16(o[2 * nb + 1], ph, v2, v3);
            }
        }
    }

    // ---- epilogue: normalize, enc -> single fp16 (A of out GEMM)
    __half* encH = (__half*)g_Ahi;
    float i1 = 1.f / l1, i2 = 1.f / l2;
#pragma unroll
    for (int nf = 0; nf < 16; ++nf) {
        int col = n * 256 + wn * 128 + nf * 8 + ccol;
        size_t o1 = (tb + q0 + grow1) * (size_t)DD + col;
        size_t o2 = (tb + q0 + grow2) * (size_t)DD + col;
        *(__half2*)&encH[o1] = __floats2half2_rn(o[nf][0] * i1, o[nf][1] * i1);
        *(__half2*)&encH[o2] = __floats2half2_rn(o[nf][2] * i2, o[nf][3] * i2);
    }
}

// ===========================================================================
// launch — inputs: 0=x, 1=segment_pos, 2=attn_mask, 3=q_w, 4=kv_w, 5=out_w
// ===========================================================================
extern "C" void kernel_launch(void* const* d_in, const int* in_sizes, int n_in,
                              void* d_out, int out_size) {
    (void)in_sizes; (void)n_in; (void)out_size;
    const float* x   = (const float*)d_in[0];
    const float* qw  = (const float*)d_in[3];
    const float* kvw = (const float*)d_in[4];
    const float* ow  = (const float*)d_in[5];
    float* out = (float*)d_out;

    cudaFuncSetAttribute(gemm_qkv_kernel,
                         cudaFuncAttributeMaxDynamicSharedMemorySize, GSM_TOTAL);
    cudaFuncSetAttribute(gemm_out_kernel,
                         cudaFuncAttributeMaxDynamicSharedMemorySize, G2SM);
    cudaFuncSetAttribute(flash_hmma,
                         cudaFuncAttributeMaxDynamicSharedMemorySize, FLASH_SMEM);

    rope_table<<<128, 256>>>();
    transpose_qkvw<<<dim3(HD / 32, DD / 32, 10), dim3(32, 8)>>>(qw, kvw);
    convert_split<<<(TOK * DD) / 4 / 256, 256>>>(x);

    // QKV projection (3xBF16) + fused rope/convert epilogue
    gemm_qkv_kernel<<<dim3(NQKV / 128, TOK / 128), 256, GSM_TOTAL>>>();

    // out weights -> fp16 hi/lo (after qkv gemm consumed bf16 weights)
    transpose_outw<<<dim3(DD / 32, DD / 32), dim3(32, 8)>>>(ow);

    // Flash attention (QK 2xfp16, PV fp16) -> enc fp16
    flash_hmma<<<dim3(TT / 64, NHEAD, BB), 256, FLASH_SMEM>>>();

    // Out projection (2xFP16)
    gemm_out_kernel<<<dim3(DD / 128, TOK / 128), 256, G2SM>>>(out);
}

// round 17
// speedup vs baseline: 1.6838x; 1.2138x over previous
#include <cuda_runtime.h>
#include <cuda_bf16.h>
#include <cuda_fp16.h>
#include <math.h>
#include <stdint.h>

// Problem constants
#define BB 2
#define TT 4096
#define DD 2048
#define NHEAD 8
#define HD 256
#define TOK (BB*TT)           // 8192
#define NQKV 2560             // 8*256 Q + 256 K + 256 V

// ---------------- scratch (device globals; no allocation allowed) ----------
__device__ __nv_bfloat16 g_Qsp[(size_t)2 * TOK * DD];   // Q fp16 single (reinterp)
__device__ __nv_bfloat16 g_Ahi[(size_t)TOK * DD];       // x fp16; later enc fp16
__device__ __nv_bfloat16 g_Alo[(size_t)TOK * DD];       // (unused this round)
__device__ __nv_bfloat16 g_Bhi[(size_t)NQKV * DD];      // weights hi fp16
__device__ __nv_bfloat16 g_Blo[(size_t)NQKV * DD];      // weights lo fp16 (qkv only)
__device__ __nv_bfloat16 g_Khi[(size_t)TOK * HD];       // K fp16 hi (reinterp)
__device__ __nv_bfloat16 g_Klo[(size_t)TOK * HD];       // K fp16 lo (reinterp)
__device__ __half        g_Vh [(size_t)TOK * HD];
__device__ float2        g_ropetab[(size_t)TT * 128];

// =================== ptx helpers ========================
__device__ __forceinline__ uint32_t s2u(const void* p) {
    uint32_t a;
    asm("{ .reg .u64 t; cvta.to.shared.u64 t, %1; cvt.u32.u64 %0, t; }"
        : "=r"(a) : "l"(p));
    return a;
}
__device__ __forceinline__ void cpa16(uint32_t s, const void* g) {
    asm volatile("cp.async.cg.shared.global [%0], [%1], 16;" :: "r"(s), "l"(g));
}
#define CP_COMMIT()  asm volatile("cp.async.commit_group;" ::: "memory")
#define CP_WAIT(N)   asm volatile("cp.async.wait_group %0;" :: "n"(N) : "memory")

#define LDSM4(r0, r1, r2, r3, addr) \
    asm volatile("ldmatrix.sync.aligned.m8n8.x4.shared.b16 {%0,%1,%2,%3}, [%4];" \
                 : "=r"(r0), "=r"(r1), "=r"(r2), "=r"(r3) : "r"(addr))

#define LDSM4T(r0, r1, r2, r3, addr) \
    asm volatile("ldmatrix.sync.aligned.m8n8.x4.trans.shared.b16 {%0,%1,%2,%3}, [%4];" \
                 : "=r"(r0), "=r"(r1), "=r"(r2), "=r"(r3) : "r"(addr))

#define MMAF16(d, a, b0, b1) \
    asm volatile("mma.sync.aligned.m16n8k16.row.col.f32.f16.f16.f32 " \
                 "{%0,%1,%2,%3}, {%4,%5,%6,%7}, {%8,%9}, {%0,%1,%2,%3};" \
                 : "+f"((d)[0]), "+f"((d)[1]), "+f"((d)[2]), "+f"((d)[3]) \
                 : "r"((a)[0]), "r"((a)[1]), "r"((a)[2]), "r"((a)[3]), \
                   "r"(b0), "r"(b1))

// ===========================================================================
// RoPE table
// ===========================================================================
__global__ void rope_table() {
    __shared__ double u1s;
    const int i = blockIdx.x;
    if (threadIdx.x == 0)
        u1s = pow(10000.0, -(double)i / 128.0) * 0.15915494309189533576;
    __syncthreads();
    const double u1 = u1s;
    for (int t = threadIdx.x; t < TT; t += blockDim.x) {
        double u = (double)t * u1;
        float x2 = (float)(2.0 * (u - trunc(u)));
        float s, c;
        sincospif(x2, &s, &c);
        g_ropetab[t * 128 + i] = make_float2(s, c);
    }
}

// ===========================================================================
// Weight prep — qkv weights -> fp16 hi/lo (interleaved Q/K heads)
// ===========================================================================
__global__ void transpose_qkvw(const float* __restrict__ qw,
                               const float* __restrict__ kvw) {
    __shared__ float t[32][33];
    const int g = blockIdx.z;
    const float* slab = (g < 8) ? qw + (size_t)g * DD * HD
                                : kvw + (size_t)(g - 8) * DD * HD;
    const int h0 = blockIdx.x * 32, k0 = blockIdx.y * 32;
    const int c = threadIdx.x, r0 = threadIdx.y;
    __half* bh = (__half*)g_Bhi;
    __half* bl = (__half*)g_Blo;
#pragma unroll
    for (int i = 0; i < 32; i += 8)
        t[r0 + i][c] = slab[(size_t)(k0 + r0 + i) * HD + h0 + c];
    __syncthreads();
#pragma unroll
    for (int i = 0; i < 32; i += 8) {
        float v = t[c][r0 + i];
        int h = h0 + r0 + i;
        int hp = (g == 9) ? h : ((h < 128) ? 2 * h : 2 * (h - 128) + 1);
        size_t o = (size_t)(g * 256 + hp) * DD + k0 + c;
        __half hi = __float2half_rn(v);
        bh[o] = hi;
        bl[o] = __float2half_rn(v - __half2float(hi));
    }
}

// out_w -> single fp16, K-major [d][nh]
__global__ void transpose_outw(const float* __restrict__ ow) {
    __shared__ float t[32][33];
    const int j0 = blockIdx.x * 32, k0 = blockIdx.y * 32;
    const int c = threadIdx.x, r0 = threadIdx.y;
    __half* bh = (__half*)g_Bhi;
#pragma unroll
    for (int i = 0; i < 32; i += 8)
        t[r0 + i][c] = ow[(size_t)(k0 + r0 + i) * DD + j0 + c];
    __syncthreads();
#pragma unroll
    for (int i = 0; i < 32; i += 8) {
        float v = t[c][r0 + i];
        bh[(size_t)(j0 + r0 + i) * DD + k0 + c] = __float2half_rn(v);
    }
}

// x -> single fp16 into g_Ahi
__global__ void convert_x(const float* __restrict__ src) {
    size_t i = (size_t)blockIdx.x * blockDim.x + threadIdx.x;   // float4 index
    float4 v = ((const float4*)src)[i];
    __half2* h2 = (__half2*)g_Ahi;
    h2[2 * i]     = __floats2half2_rn(v.x, v.y);
    h2[2 * i + 1] = __floats2half2_rn(v.z, v.w);
}

// ===========================================================================
// QKV GEMM — 2xFP16 (A = x single fp16, B = fp16 hi+lo), 2-stage ring,
// 2 CTAs/SM.  Fused epilogue: Q->fp16 (rope+scale), K->fp16 hi/lo, V->fp16.
// ===========================================================================
#define KC 32
#define TROW 80
#define TILEB (128 * TROW)              // 10240
#define STAGE3B (3 * TILEB)             // 30720 (A, Bhi, Blo)
#define GQSM (2 * STAGE3B)              // 61440

__device__ __forceinline__ void load_stage3(uint32_t smb, int s, int k0, int tid,
                                            const __half* a,
                                            const __half* bh, const __half* bl) {
    uint32_t sb = smb + s * STAGE3B;
#pragma unroll
    for (int j = 0; j < 6; ++j) {
        int c = tid + j * 256;
        const int tile = j >> 1;
        int inner = c & 511;
        int row = inner >> 2, seg = inner & 3;
        const __half* gp = (tile == 0 ? a : tile == 1 ? bh : bl)
                           + (size_t)row * DD + k0 + seg * 8;
        cpa16(sb + tile * TILEB + row * TROW + seg * 16, gp);
    }
    CP_COMMIT();
}

__global__ __launch_bounds__(256, 2) void gemm_qkv_kernel() {
    extern __shared__ __align__(128) char sm[];
    uint32_t smb = s2u(sm);
    const int tid = threadIdx.x;
    const int lane = tid & 31, wid = tid >> 5;
    const int wm = wid & 1, wn = wid >> 1;
    const int n0 = blockIdx.x * 128;
    const int m0 = blockIdx.y * 128;

    const __half* aB = (const __half*)g_Ahi + (size_t)m0 * DD;
    const __half* bH = (const __half*)g_Bhi + (size_t)n0 * DD;
    const __half* bL = (const __half*)g_Blo + (size_t)n0 * DD;

    float acc[4][4][4];
#pragma unroll
    for (int i = 0; i < 4; ++i)
#pragma unroll
        for (int j = 0; j < 4; ++j)
#pragma unroll
            for (int r = 0; r < 4; ++r) acc[i][j][r] = 0.f;

    const uint32_t a_off = (uint32_t)((wm * 64 + (lane & 15)) * TROW
                                      + (lane >> 4) * 16);
    const uint32_t b_off = (uint32_t)((wn * 32 + (lane >> 4) * 8 + (lane & 7)) * TROW
                                      + ((lane >> 3) & 1) * 16);

    load_stage3(smb, 0, 0, tid, aB, bH, bL);

    const int NIT = DD / KC;
    for (int it = 0; it < NIT; ++it) {
        const int s = it & 1;
        if (it + 1 < NIT) {
            load_stage3(smb, s ^ 1, (it + 1) * KC, tid, aB, bH, bL);
            CP_WAIT(1);
        } else {
            CP_WAIT(0);
        }
        __syncthreads();

        const uint32_t st = smb + s * STAGE3B;
#pragma unroll
        for (int ks = 0; ks < 2; ++ks) {
            const uint32_t ko = ks * 32;
            uint32_t bhi[4][2], blo[4][2];
#pragma unroll
            for (int pr = 0; pr < 2; ++pr) {
                uint32_t ba = st + TILEB + b_off + pr * (16 * TROW) + ko;
                LDSM4(bhi[2 * pr][0], bhi[2 * pr][1],
                      bhi[2 * pr + 1][0], bhi[2 * pr + 1][1], ba);
                LDSM4(blo[2 * pr][0], blo[2 * pr][1],
                      blo[2 * pr + 1][0], blo[2 * pr + 1][1], ba + TILEB);
            }
#pragma unroll
            for (int mf = 0; mf < 4; ++mf) {
                uint32_t af[4];
                LDSM4(af[0], af[1], af[2], af[3],
                      st + a_off + mf * (16 * TROW) + ko);
#pragma unroll
                for (int nf = 0; nf < 4; ++nf) {
                    MMAF16(acc[mf][nf], af, bhi[nf][0], bhi[nf][1]);
                    MMAF16(acc[mf][nf], af, blo[nf][0], blo[nf][1]);
                }
            }
        }
        __syncthreads();
    }

    const int r0 = m0 + wm * 64 + (lane >> 2);
    const int lc0 = wn * 32 + 2 * (lane & 3);

    if (n0 < 2048) {
        // Q: rope + 1/16 scale -> single fp16 (cols interleaved)
        __half* Qh = (__half*)g_Qsp;
#pragma unroll
        for (int mf = 0; mf < 4; ++mf)
#pragma unroll
            for (int nf = 0; nf < 4; ++nf) {
                int row1 = r0 + mf * 16, row2 = row1 + 8;
                int col = n0 + lc0 + nf * 8;
                int ri = (col & 255) >> 1;
                float2 sc1 = g_ropetab[(row1 & (TT - 1)) * 128 + ri];
                float2 sc2 = g_ropetab[(row2 & (TT - 1)) * 128 + ri];
                float a1 = acc[mf][nf][0], b1 = acc[mf][nf][1];
                float a2 = acc[mf][nf][2], b2 = acc[mf][nf][3];
                float x1 = (a1 * sc1.y - b1 * sc1.x) * 0.0625f;
                float y1 = (b1 * sc1.y + a1 * sc1.x) * 0.0625f;
                float x2 = (a2 * sc2.y - b2 * sc2.x) * 0.0625f;
                float y2 = (b2 * sc2.y + a2 * sc2.x) * 0.0625f;
                *(__half2*)&Qh[(size_t)row1 * DD + col] = __floats2half2_rn(x1, y1);
                *(__half2*)&Qh[(size_t)row2 * DD + col] = __floats2half2_rn(x2, y2);
            }
    } else if (n0 < 2304) {
        // K: rope -> fp16 hi/lo (cols interleaved)
        __half* Kh = (__half*)g_Khi;
        __half* Kl = (__half*)g_Klo;
#pragma unroll
        for (int mf = 0; mf < 4; ++mf)
#pragma unroll
            for (int nf = 0; nf < 4; ++nf) {
                int row1 = r0 + mf * 16, row2 = row1 + 8;
                int col = (n0 - 2048) + lc0 + nf * 8;
                int ri = col >> 1;
                float2 sc1 = g_ropetab[(row1 & (TT - 1)) * 128 + ri];
                float2 sc2 = g_ropetab[(row2 & (TT - 1)) * 128 + ri];
                float a1 = acc[mf][nf][0], b1 = acc[mf][nf][1];
                float a2 = acc[mf][nf][2], b2 = acc[mf][nf][3];
                float x1 = a1 * sc1.y - b1 * sc1.x;
                float y1 = b1 * sc1.y + a1 * sc1.x;
                float x2 = a2 * sc2.y - b2 * sc2.x;
                float y2 = b2 * sc2.y + a2 * sc2.x;
                __half hx1 = __float2half_rn(x1), hy1 = __float2half_rn(y1);
                __half hx2 = __float2half_rn(x2), hy2 = __float2half_rn(y2);
                *(__half2*)&Kh[(size_t)row1 * HD + col] = __halves2half2(hx1, hy1);
                *(__half2*)&Kh[(size_t)row2 * HD + col] = __halves2half2(hx2, hy2);
                *(__half2*)&Kl[(size_t)row1 * HD + col] = __halves2half2(
                    __float2half_rn(x1 - __half2float(hx1)),
                    __float2half_rn(y1 - __half2float(hy1)));
                *(__half2*)&Kl[(size_t)row2 * HD + col] = __halves2half2(
                    __float2half_rn(x2 - __half2float(hx2)),
                    __float2half_rn(y2 - __half2float(hy2)));
            }
    } else {
#pragma unroll
        for (int mf = 0; mf < 4; ++mf)
#pragma unroll
            for (int nf = 0; nf < 4; ++nf) {
                int row1 = r0 + mf * 16, row2 = row1 + 8;
                int col = (n0 - 2304) + lc0 + nf * 8;
                *(__half2*)&g_Vh[(size_t)row1 * HD + col] =
                    __floats2half2_rn(acc[mf][nf][0], acc[mf][nf][1]);
                *(__half2*)&g_Vh[(size_t)row2 * HD + col] =
                    __floats2half2_rn(acc[mf][nf][2], acc[mf][nf][3]);
            }
    }
}

// ===========================================================================
// OUT GEMM — 1xFP16 (A = enc fp16, B = out_w fp16), 2-stage ring, 2 CTAs/SM.
// ===========================================================================
#define STAGE2B (2 * TILEB)             // 20480 (A, B)
#define G2SM (2 * STAGE2B)              // 40960

__device__ __forceinline__ void load_stage2(uint32_t smb, int s, int k0, int tid,
                                            const __half* a, const __half* bh) {
    uint32_t sb = smb + s * STAGE2B;
#pragma unroll
    for (int j = 0; j < 4; ++j) {
        int c = tid + j * 256;
        const int tile = j >> 1;
        int inner = c & 511;
        int row = inner >> 2, seg = inner & 3;
        const __half* gp = (tile == 0 ? a : bh) + (size_t)row * DD + k0 + seg * 8;
        cpa16(sb + tile * TILEB + row * TROW + seg * 16, gp);
    }
    CP_COMMIT();
}

__global__ __launch_bounds__(256, 2) void gemm_out_kernel(float* outp) {
    extern __shared__ __align__(128) char sm[];
    uint32_t smb = s2u(sm);
    const int tid = threadIdx.x;
    const int lane = tid & 31, wid = tid >> 5;
    const int wm = wid & 1, wn = wid >> 1;
    const int n0 = blockIdx.x * 128;
    const int m0 = blockIdx.y * 128;

    const __half* aB = (const __half*)g_Ahi + (size_t)m0 * DD;
    const __half* bH = (const __half*)g_Bhi + (size_t)n0 * DD;

    float acc[4][4][4];
#pragma unroll
    for (int i = 0; i < 4; ++i)
#pragma unroll
        for (int j = 0; j < 4; ++j)
#pragma unroll
            for (int r = 0; r < 4; ++r) acc[i][j][r] = 0.f;

    const uint32_t a_off = (uint32_t)((wm * 64 + (lane & 15)) * TROW
                                      + (lane >> 4) * 16);
    const uint32_t b_off = (uint32_t)((wn * 32 + (lane >> 4) * 8 + (lane & 7)) * TROW
                                      + ((lane >> 3) & 1) * 16);

    load_stage2(smb, 0, 0, tid, aB, bH);

    const int NIT = DD / KC;
    for (int it = 0; it < NIT; ++it) {
        const int s = it & 1;
        if (it + 1 < NIT) {
            load_stage2(smb, s ^ 1, (it + 1) * KC, tid, aB, bH);
            CP_WAIT(1);
        } else {
            CP_WAIT(0);
        }
        __syncthreads();

        const uint32_t st = smb + s * STAGE2B;
#pragma unroll
        for (int ks = 0; ks < 2; ++ks) {
            const uint32_t ko = ks * 32;
            uint32_t bhi[4][2];
#pragma unroll
            for (int pr = 0; pr < 2; ++pr) {
                uint32_t ba = st + TILEB + b_off + pr * (16 * TROW) + ko;
                LDSM4(bhi[2 * pr][0], bhi[2 * pr][1],
                      bhi[2 * pr + 1][0], bhi[2 * pr + 1][1], ba);
            }
#pragma unroll
            for (int mf = 0; mf < 4; ++mf) {
                uint32_t af[4];
                LDSM4(af[0], af[1], af[2], af[3],
                      st + a_off + mf * (16 * TROW) + ko);
#pragma unroll
                for (int nf = 0; nf < 4; ++nf)
                    MMAF16(acc[mf][nf], af, bhi[nf][0], bhi[nf][1]);
            }
        }
        __syncthreads();
    }

    const int r0 = m0 + wm * 64 + (lane >> 2);
    const int c0 = n0 + wn * 32 + 2 * (lane & 3);
#pragma unroll
    for (int mf = 0; mf < 4; ++mf)
#pragma unroll
        for (int nf = 0; nf < 4; ++nf) {
            float* p0 = outp + (size_t)(r0 + mf * 16) * DD + c0 + nf * 8;
            *(float2*)p0 = make_float2(acc[mf][nf][0], acc[mf][nf][1]);
            float* p1 = p0 + 8 * DD;
            *(float2*)p1 = make_float2(acc[mf][nf][2], acc[mf][nf][3]);
        }
}

// ===========================================================================
// Flash attention — BN=64, QK = 2xFP16 (Q single, K hi+lo), PV fp16.
// (unchanged from R16)
// ===========================================================================
#define BN 64
#define KST 528
#define PST 144
#define KSTAGE 67584
#define ST_KHI(s) ((s)*KSTAGE)
#define ST_KLO(s) (ST_KHI(s)+33792)
#define SVH    (2*KSTAGE)                  // 135168
#define SPHI   (SVH + 33792)               // 168960
#define SRED   (SPHI + 64*PST)             // 178176
#define FLASH_SMEM (SRED + 1024)           // 179200

__device__ __forceinline__ void flash_load_k(uint32_t smb, int s, int s0, int tid,
                                             const __half* kh, const __half* kl) {
#pragma unroll
    for (int i2 = 0; i2 < 8; ++i2) {
        int c = tid + i2 * 256;
        int row = c >> 5, seg = c & 31;
        size_t go = (size_t)(s0 + row) * 512 + seg * 16;
        uint32_t so = row * KST + seg * 16;
        cpa16(smb + ST_KHI(s) + so, (const char*)kh + go);
        cpa16(smb + ST_KLO(s) + so, (const char*)kl + go);
    }
    CP_COMMIT();
}

__device__ __forceinline__ void flash_load_v(uint32_t smb, int s0, int tid,
                                             const __half* vh) {
#pragma unroll
    for (int i2 = 0; i2 < 8; ++i2) {
        int c = tid + i2 * 256;
        int row = c >> 5, seg = c & 31;
        cpa16(smb + SVH + row * KST + seg * 16,
              (const char*)vh + (size_t)(s0 + row) * 512 + seg * 16);
    }
    CP_COMMIT();
}

__global__ __launch_bounds__(256) void flash_hmma() {
    extern __shared__ __align__(128) char sm[];
    uint32_t smb = s2u(sm);
    const int tid = threadIdx.x, lane = tid & 31, wid = tid >> 5;
    const int wm = wid >> 1, wn = wid & 1;
    const int bx = gridDim.x - 1 - blockIdx.x;
    const int n = blockIdx.y, b = blockIdx.z;
    const int q0 = bx * 64;
    const size_t tb = (size_t)b * TT;

    const char* qh_g = (const char*)((const __half*)g_Qsp
                                     + (size_t)(tb + q0) * DD + n * 256);
    const __half* kh_g = (const __half*)g_Khi + tb * 256;
    const __half* kl_g = (const __half*)g_Klo + tb * 256;
    const __half* vh_g = g_Vh + tb * 256;

#pragma unroll
    for (int i2 = 0; i2 < 8; ++i2) {
        int c = tid + i2 * 256;
        int row = c >> 5, seg = c & 31;
        cpa16(smb + ST_KHI(1) + row * KST + seg * 16,
              qh_g + (size_t)row * 4096 + seg * 16);
    }
    CP_COMMIT();
    CP_WAIT(0);
    __syncthreads();

    const uint32_t a_base = (uint32_t)((wm * 16 + (lane & 15)) * KST + (lane >> 4) * 16);
    uint32_t qh[16][4];
#pragma unroll
    for (int ks = 0; ks < 16; ++ks)
        LDSM4(qh[ks][0], qh[ks][1], qh[ks][2], qh[ks][3],
              smb + ST_KHI(1) + a_base + ks * 32);
    flash_load_k(smb, 0, 0, tid, kh_g, kl_g);

    float o[16][4];
#pragma unroll
    for (int nf = 0; nf < 16; ++nf)
#pragma unroll
        for (int r = 0; r < 4; ++r) o[nf][r] = 0.f;
    float m1 = -1e30f, m2 = -1e30f, l1 = 0.f, l2 = 0.f;

    const int grow1 = wm * 16 + (lane >> 2);
    const int grow2 = grow1 + 8;
    const int ccol = 2 * (lane & 3);
    float* rmaxs = (float*)(sm + SRED);
    float* rsums = (float*)(sm + SRED + 512);
    const uint32_t b_base = (uint32_t)((wn * 32 + ((lane >> 4) << 3) + (lane & 7)) * KST
                                       + ((lane >> 3) & 1) * 16);
    const uint32_t p_base = (uint32_t)((wm * 16 + (lane & 15)) * PST + (lane >> 4) * 16);
    const uint32_t v_base = (uint32_t)((lane & 15) * KST + wn * 256 + (lane >> 4) * 16);

    const int ntiles = bx + 1;
    for (int kt = 0; kt < ntiles; ++kt) {
        const int s = kt & 1;
        const bool haveK = (kt + 1 < ntiles);
        __syncthreads();
        flash_load_v(smb, kt * BN, tid, vh_g);
        if (haveK) {
            flash_load_k(smb, s ^ 1, (kt + 1) * BN, tid, kh_g, kl_g);
            CP_WAIT(2);
        } else {
            CP_WAIT(1);
        }
        __syncthreads();

        float sa[4][4];
#pragma unroll
        for (int nf = 0; nf < 4; ++nf)
#pragma unroll
            for (int r = 0; r < 4; ++r) sa[nf][r] = 0.f;
#pragma unroll
        for (int ks = 0; ks < 16; ++ks) {
            uint32_t bh[8], bl[8];
#pragma unroll
            for (int pr = 0; pr < 2; ++pr) {
                uint32_t ba = smb + ST_KHI(s) + b_base + pr * (16 * KST) + ks * 32;
                LDSM4(bh[4 * pr + 0], bh[4 * pr + 1], bh[4 * pr + 2], bh[4 * pr + 3], ba);
                LDSM4(bl[4 * pr + 0], bl[4 * pr + 1], bl[4 * pr + 2], bl[4 * pr + 3],
                      ba + 33792);
            }
#pragma unroll
            for (int nf = 0; nf < 4; ++nf) {
                MMAF16(sa[nf], qh[ks], bh[2 * nf], bh[2 * nf + 1]);
                MMAF16(sa[nf], qh[ks], bl[2 * nf], bl[2 * nf + 1]);
            }
        }

        const int s0 = kt * BN;
        if (kt == bx) {
            const int qr1 = q0 + grow1, qr2 = q0 + grow2;
#pragma unroll
            for (int nf = 0; nf < 4; ++nf) {
                int c0 = s0 + wn * 32 + nf * 8 + ccol;
                if (c0     > qr1) sa[nf][0] = -1e30f;
                if (c0 + 1 > qr1) sa[nf][1] = -1e30f;
                if (c0     > qr2) sa[nf][2] = -1e30f;
                if (c0 + 1 > qr2) sa[nf][3] = -1e30f;
            }
        }

        float pm1 = -1e30f, pm2 = -1e30f;
#pragma unroll
        for (int nf = 0; nf < 4; ++nf) {
            pm1 = fmaxf(pm1, fmaxf(sa[nf][0], sa[nf][1]));
            pm2 = fmaxf(pm2, fmaxf(sa[nf][2], sa[nf][3]));
        }
        pm1 = fmaxf(pm1, __shfl_xor_sync(0xffffffffu, pm1, 1));
        pm1 = fmaxf(pm1, __shfl_xor_sync(0xffffffffu, pm1, 2));
        pm2 = fmaxf(pm2, __shfl_xor_sync(0xffffffffu, pm2, 1));
        pm2 = fmaxf(pm2, __shfl_xor_sync(0xffffffffu, pm2, 2));
        if ((lane & 3) == 0) {
            rmaxs[wn * 64 + grow1] = pm1;
            rmaxs[wn * 64 + grow2] = pm2;
        }
        __syncthreads();
        float mn1 = fmaxf(m1, fmaxf(rmaxs[grow1], rmaxs[64 + grow1]));
        float mn2 = fmaxf(m2, fmaxf(rmaxs[grow2], rmaxs[64 + grow2]));
        float al1 = __expf(m1 - mn1), al2 = __expf(m2 - mn2);
        m1 = mn1; m2 = mn2;

        float ps1 = 0.f, ps2 = 0.f;
#pragma unroll
        for (int nf = 0; nf < 4; ++nf) {
            float e0 = __expf(sa[nf][0] - mn1), e1 = __expf(sa[nf][1] - mn1);
            float e2 = __expf(sa[nf][2] - mn2), e3 = __expf(sa[nf][3] - mn2);
            ps1 += e0 + e1; ps2 += e2 + e3;
            int colB = (wn * 32 + nf * 8 + ccol) * 2;
            *(__half2*)(sm + SPHI + grow1 * PST + colB) = __floats2half2_rn(e0, e1);
            *(__half2*)(sm + SPHI + grow2 * PST + colB) = __floats2half2_rn(e2, e3);
        }
        ps1 += __shfl_xor_sync(0xffffffffu, ps1, 1);
        ps1 += __shfl_xor_sync(0xffffffffu, ps1, 2);
        ps2 += __shfl_xor_sync(0xffffffffu, ps2, 1);
        ps2 += __shfl_xor_sync(0xffffffffu, ps2, 2);
        if ((lane & 3) == 0) {
            rsums[wn * 64 + grow1] = ps1;
            rsums[wn * 64 + grow2] = ps2;
        }
#pragma unroll
        for (int nf = 0; nf < 16; ++nf) {
            o[nf][0] *= al1; o[nf][1] *= al1;
            o[nf][2] *= al2; o[nf][3] *= al2;
        }
        if (haveK) { CP_WAIT(1); } else { CP_WAIT(0); }
        __syncthreads();
        l1 = l1 * al1 + rsums[grow1] + rsums[64 + grow1];
        l2 = l2 * al2 + rsums[grow2] + rsums[64 + grow2];

#pragma unroll
        for (int ks = 0; ks < 4; ++ks) {
            uint32_t ph[4];
            LDSM4(ph[0], ph[1], ph[2], ph[3], smb + SPHI + p_base + ks * 32);
#pragma unroll
            for (int nb = 0; nb < 8; ++nb) {
                uint32_t v0, v1, v2, v3;
                LDSM4T(v0, v1, v2, v3,
                       smb + SVH + v_base + ks * (16 * KST) + nb * 32);
                MMAF16(o[2 * nb],     ph, v0, v1);
                MMAF16(o[2 * nb + 1], ph, v2, v3);
            }
        }
    }

    __half* encH = (__half*)g_Ahi;
    float i1 = 1.f / l1, i2 = 1.f / l2;
#pragma unroll
    for (int nf = 0; nf < 16; ++nf) {
        int col = n * 256 + wn * 128 + nf * 8 + ccol;
        size_t o1 = (tb + q0 + grow1) * (size_t)DD + col;
        size_t o2 = (tb + q0 + grow2) * (size_t)DD + col;
        *(__half2*)&encH[o1] = __floats2half2_rn(o[nf][0] * i1, o[nf][1] * i1);
        *(__half2*)&encH[o2] = __floats2half2_rn(o[nf][2] * i2, o[nf][3] * i2);
    }
}

// ===========================================================================
// launch — inputs: 0=x, 1=segment_pos, 2=attn_mask, 3=q_w, 4=kv_w, 5=out_w
// ===========================================================================
extern "C" void kernel_launch(void* const* d_in, const int* in_sizes, int n_in,
                              void* d_out, int out_size) {
    (void)in_sizes; (void)n_in; (void)out_size;
    const float* x   = (const float*)d_in[0];
    const float* qw  = (const float*)d_in[3];
    const float* kvw = (const float*)d_in[4];
    const float* ow  = (const float*)d_in[5];
    float* out = (float*)d_out;

    cudaFuncSetAttribute(gemm_qkv_kernel,
                         cudaFuncAttributeMaxDynamicSharedMemorySize, GQSM);
    cudaFuncSetAttribute(gemm_out_kernel,
                         cudaFuncAttributeMaxDynamicSharedMemorySize, G2SM);
    cudaFuncSetAttribute(flash_hmma,
                         cudaFuncAttributeMaxDynamicSharedMemorySize, FLASH_SMEM);

    rope_table<<<128, 256>>>();
    transpose_qkvw<<<dim3(HD / 32, DD / 32, 10), dim3(32, 8)>>>(qw, kvw);
    convert_x<<<(TOK * DD) / 4 / 256, 256>>>(x);

    // QKV projection (2xFP16) + fused rope/convert epilogue
    gemm_qkv_kernel<<<dim3(NQKV / 128, TOK / 128), 256, GQSM>>>();

    // out weights -> single fp16 (after qkv gemm consumed split weights)
    transpose_outw<<<dim3(DD / 32, DD / 32), dim3(32, 8)>>>(ow);

    // Flash attention (QK 2xfp16, PV fp16) -> enc fp16
    flash_hmma<<<dim3(TT / 64, NHEAD, BB), 256, FLASH_SMEM>>>();

    // Out projection (1xFP16)
    gemm_out_kernel<<<dim3(DD / 128, TOK / 128), 256, G2SM>>>(out);
}